// round 12
// baseline (speedup 1.0000x reference)
#include <cuda_runtime.h>
#include <cstdint>
#include <math.h>

// ---------------------------------------------------------------------------
// LSTM  B=64 S=512 D=1024 H=1024 F=1024
//  1) G_pre = Xt @ WxT^T + b_g      (tf32 GEMM, M=32768 N=4096 K=1024)
//  2) ONE persistent kernel, 128 CTAs x 1024 thr, 512 steps:
//       gates = G_pre[t] + h@WhT^T ; fused LSTM elementwise
//     Intra-CTA split-K x4: warpgroup wg does K[wg*256,(wg+1)*256);
//     partials combined in smem gate exchange. W_h slice fragment-packed in
//     SMEM; BK=16, 4-stage cp.async ring (stride-20 rows, conflict-free);
//     c in registers; flat all-poll grid barrier.
//  3) out = Hall @ WoT^T + b_out    (tf32 GEMM, M=32768 N=1024 K=1024)
// Gate columns interleaved: n = 4*unit + gate.
// ---------------------------------------------------------------------------

#define DEVINL __device__ __forceinline__

// ---------------- static device scratch (no runtime allocation) ------------
__device__ float g_Xt  [(size_t)32768 * 1024];   // x as (t,b) rows, tf32-rounded
__device__ float g_Gpre[(size_t)32768 * 4096];   // x-part of gates (+bias)
__device__ float g_Hall[(size_t)32768 * 1024];   // all h_t, tf32-rounded
__device__ float g_WxT [(size_t)4096 * 1024];    // [n][k] interleaved, x rows
__device__ float g_WhT [(size_t)4096 * 1024];    // [n][k] interleaved, h rows
__device__ float g_WoT [(size_t)1024 * 1024];    // W_out^T [f][h]
__device__ float g_bg  [4096];                   // gate bias, interleaved
__device__ float g_h0  [64 * 1024];              // initial h (tf32-rounded)
__device__ float g_c   [64 * 1024];              // cell state (init only)

// grid-barrier state: monotonic counters (never reset; base read per launch)
__device__ unsigned g_flags[128 * 32];           // flag i at [i*32] (own 128B line)

// ---------------- helpers ---------------------------------------------------
DEVINL uint32_t f2tf32(float x) {
    uint32_t r; asm("cvt.rna.tf32.f32 %0, %1;" : "=r"(r) : "f"(x)); return r;
}
DEVINL float tf32r(float x) { return __uint_as_float(f2tf32(x)); }

DEVINL void cpa16(void* dst, const void* src) {
    uint32_t d = (uint32_t)__cvta_generic_to_shared(dst);
    asm volatile("cp.async.cg.shared.global [%0], [%1], 16;\n" :: "r"(d), "l"(src));
}
DEVINL void cp_commit() { asm volatile("cp.async.commit_group;\n"); }
template <int N> DEVINL void cp_wait() { asm volatile("cp.async.wait_group %0;\n" :: "n"(N)); }

DEVINL void mma_tf32(float* c, const uint32_t* a, const uint32_t* b) {
    asm volatile(
        "mma.sync.aligned.m16n8k8.row.col.f32.tf32.tf32.f32 "
        "{%0,%1,%2,%3},{%4,%5,%6,%7},{%8,%9},{%0,%1,%2,%3};\n"
        : "+f"(c[0]), "+f"(c[1]), "+f"(c[2]), "+f"(c[3])
        : "r"(a[0]), "r"(a[1]), "r"(a[2]), "r"(a[3]), "r"(b[0]), "r"(b[1]));
}
DEVINL float sigm(float x)   { return 1.f / (1.f + __expf(-x)); }
DEVINL float tanh_f(float x) { return 2.f / (1.f + __expf(-2.f * x)) - 1.f; }

DEVINL unsigned ldacq(const unsigned* p) {
    unsigned v; asm volatile("ld.acquire.gpu.global.u32 %0, [%1];" : "=r"(v) : "l"(p)); return v;
}
DEVINL void strel(unsigned* p, unsigned v) {
    asm volatile("st.release.gpu.global.u32 [%0], %1;" :: "l"(p), "r"(v));
}

// ---------------- prepA: x transform + bias/state init ----------------------
__global__ void __launch_bounds__(256) k_prepA(
        const float* __restrict__ x,
        const float* __restrict__ bf, const float* __restrict__ bi,
        const float* __restrict__ bc, const float* __restrict__ bo,
        const float* __restrict__ h0, const float* __restrict__ c0) {
    if (blockIdx.x < 32768) {
        size_t p = (size_t)blockIdx.x * 256 + threadIdx.x;
        int d4 = (int)(p & 255);
        size_t m = p >> 8;
        int b = (int)(m & 63), t = (int)(m >> 6);
        float4 v = *(const float4*)(x + ((size_t)b * 512 + t) * 1024 + (size_t)d4 * 4);
        v.x = tf32r(v.x); v.y = tf32r(v.y); v.z = tf32r(v.z); v.w = tf32r(v.w);
        *(float4*)(g_Xt + m * 1024 + (size_t)d4 * 4) = v;
    } else {
        int i = (blockIdx.x - 32768) * 256 + threadIdx.x;   // 0..65535
        if (i < 4096) {
            int u = i >> 2, gt = i & 3;
            const float* b = (gt == 0) ? bf : (gt == 1) ? bi : (gt == 2) ? bc : bo;
            g_bg[i] = b[u];
        }
        g_h0[i] = tf32r(h0[i]);
        g_c[i]  = c0[i];
    }
}

// ---------------- prepB: weight transposes ----------------------------------
__global__ void k_prepB(const float* __restrict__ Wf, const float* __restrict__ Wi,
                        const float* __restrict__ Wc, const float* __restrict__ Wo,
                        const float* __restrict__ Wout) {
    __shared__ float tile[32][33];
    int tx = threadIdx.x, ty = threadIdx.y;
    if (blockIdx.x < 8192) {
        int bid = blockIdx.x;
        int s    = bid >> 12;         // 0 = x rows, 1 = h rows
        int gate = (bid >> 10) & 3;
        int kt   = (bid >> 5) & 31;
        int ut   = bid & 31;
        const float* W = (gate == 0) ? Wf : (gate == 1) ? Wi : (gate == 2) ? Wc : Wo;
#pragma unroll
        for (int r = 0; r < 4; r++) {
            int k = kt * 32 + ty + r * 8;
            tile[ty + r * 8][tx] = W[(size_t)(s * 1024 + k) * 1024 + ut * 32 + tx];
        }
        __syncthreads();
        float* WT = s ? g_WhT : g_WxT;
#pragma unroll
        for (int r = 0; r < 4; r++) {
            int ul = ty + r * 8;
            int n = 4 * (ut * 32 + ul) + gate;
            WT[(size_t)n * 1024 + kt * 32 + tx] = tf32r(tile[tx][ul]);
        }
    } else {
        int bid = blockIdx.x - 8192;
        int ft = bid & 31, ht = bid >> 5;
#pragma unroll
        for (int r = 0; r < 4; r++) {
            int h = ht * 32 + ty + r * 8;
            tile[ty + r * 8][tx] = Wout[(size_t)h * 1024 + ft * 32 + tx];
        }
        __syncthreads();
#pragma unroll
        for (int r = 0; r < 4; r++) {
            int fl = ty + r * 8;
            int f = ft * 32 + fl;
            g_WoT[(size_t)f * 1024 + ht * 32 + tx] = tf32r(tile[tx][fl]);
        }
    }
}

// ---------------- big tf32 GEMM: BM=128 BN=128 BK=32, 256 thr, 3-stage -----
static const int GEMM_SMEM = 3 * 2 * 128 * 36 * 4;   // 110592 B

__global__ void __launch_bounds__(256) k_gemm(float* __restrict__ Cpost,
                                              const float* __restrict__ bias_post,
                                              int mode) {
    extern __shared__ float sm[];
    const float* A  = mode ? g_Hall : g_Xt;
    const float* BT = mode ? g_WoT  : g_WxT;
    float* As = sm;                    // [3][128][36]
    float* Bs = sm + 3 * 128 * 36;     // [3][128][36]

    const int tid = threadIdx.x, lane = tid & 31, wid = tid >> 5;
    const int wm = wid & 1, wn = wid >> 1;          // 2 x 4 warps
    const int g = lane >> 2, tg = lane & 3;

    int mi, ni;
    if (mode == 0) {                     // 32 n-blocks
        int sup = blockIdx.x >> 8, rem = blockIdx.x & 255;
        mi = sup * 8 + (rem & 7); ni = rem >> 3;
    } else {                             // 8 n-blocks
        int sup = blockIdx.x >> 6, rem = blockIdx.x & 63;
        mi = sup * 8 + (rem & 7); ni = rem >> 3;
    }
    const int m0 = mi * 128;
    const int n0 = ni * 128;

    float acc[4][4][4];
#pragma unroll
    for (int i = 0; i < 4; i++)
#pragma unroll
        for (int j = 0; j < 4; j++)
#pragma unroll
            for (int k = 0; k < 4; k++) acc[i][j][k] = 0.f;

    auto issue = [&](int stg, int kb) {
        float* as = As + stg * 128 * 36;
        float* bs = Bs + stg * 128 * 36;
#pragma unroll
        for (int r = 0; r < 4; r++) {
            int f = tid + r * 256; int row = f >> 3, c4 = f & 7;
            cpa16(&as[row * 36 + c4 * 4],
                  A + (size_t)(m0 + row) * 1024 + kb + c4 * 4);
        }
#pragma unroll
        for (int r = 0; r < 4; r++) {
            int f = tid + r * 256; int row = f >> 3, c4 = f & 7;
            cpa16(&bs[row * 36 + c4 * 4],
                  BT + (size_t)(n0 + row) * 1024 + kb + c4 * 4);
        }
    };

    issue(0, 0);  cp_commit();
    issue(1, 32); cp_commit();

    for (int kbi = 0; kbi < 32; kbi++) {
        cp_wait<1>();
        __syncthreads();
        const uint32_t* as = (const uint32_t*)(As + (kbi % 3) * 128 * 36);
        const uint32_t* bs = (const uint32_t*)(Bs + (kbi % 3) * 128 * 36);
#pragma unroll
        for (int kk = 0; kk < 32; kk += 8) {
            uint32_t a[4][4], b[4][2];
#pragma unroll
            for (int mt = 0; mt < 4; mt++) {
                int r0 = wm * 64 + mt * 16 + g;
                a[mt][0] = as[r0 * 36 + kk + tg];
                a[mt][1] = as[(r0 + 8) * 36 + kk + tg];
                a[mt][2] = as[r0 * 36 + kk + 4 + tg];
                a[mt][3] = as[(r0 + 8) * 36 + kk + 4 + tg];
            }
#pragma unroll
            for (int nt = 0; nt < 4; nt++) {
                int nr = wn * 32 + nt * 8 + g;
                b[nt][0] = bs[nr * 36 + kk + tg];
                b[nt][1] = bs[nr * 36 + kk + 4 + tg];
            }
#pragma unroll
            for (int mt = 0; mt < 4; mt++)
#pragma unroll
                for (int nt = 0; nt < 4; nt++) mma_tf32(acc[mt][nt], a[mt], b[nt]);
        }
        if (kbi + 2 < 32) issue((kbi + 2) % 3, (kbi + 2) * 32);
        cp_commit();
    }

    // epilogue
#pragma unroll
    for (int mt = 0; mt < 4; mt++) {
#pragma unroll
        for (int nt = 0; nt < 4; nt++) {
            int row = m0 + wm * 64 + mt * 16 + g;
            int col = n0 + wn * 32 + nt * 8 + 2 * tg;
#pragma unroll
            for (int h = 0; h < 2; h++) {
                int gr = row + h * 8;
                float b0, b1;
                float v0 = acc[mt][nt][h * 2 + 0];
                float v1 = acc[mt][nt][h * 2 + 1];
                if (mode == 0) { b0 = g_bg[col]; b1 = g_bg[col + 1]; }
                else           { b0 = bias_post[col]; b1 = bias_post[col + 1]; }
                float2 v = make_float2(v0 + b0, v1 + b1);
                if (mode == 0) {
                    *(float2*)(g_Gpre + (size_t)gr * 4096 + col) = v;
                } else {
                    size_t o = ((size_t)(gr & 63) * 512 + (gr >> 6)) * 1024 + col;
                    *(float2*)(Cpost + o) = v;
                }
            }
        }
    }
}

// ---------------- persistent recurrence: 128 CTAs x 1024 thr, 512 steps ----
// CTA owns gate columns [n0, n0+32) = units [n0/4, n0/4+8).
// Split-K x4: warpgroup wg (= wid>>3) computes K[wg*256,(wg+1)*256).
// SMEM: Bf (fragment-packed W_h, 128KB)
//     | Ast: 4-stage ring, stage = [4 wgq][64][20] (BK=16, stride-20 rows)
//     | Gs (Gpre[t] tile 64x32). Partials combined in gate exchange.
static const int AST_Q     = 64 * 20;                 // 1280 floats per quarter
static const int AST_STAGE = 4 * AST_Q;               // 5120 floats per stage
static const int REC_SMEM  = (32768 + 4 * AST_STAGE + 2048) * 4;  // 221184 B

__global__ void __launch_bounds__(1024) k_rec() {
    extern __shared__ float smr[];
    float* Bf  = smr;                     // [128 k8][2 wn][32 lane][4] = 128KB
    float* Ast = smr + 32768;             // 4 stages [4][64][20]; aliased as gb
    float* Gs  = smr + 32768 + 4 * AST_STAGE;   // [64][32] Gpre tile

    const int tid = threadIdx.x, lane = tid & 31, wid = tid >> 5;
    const int wg = wid >> 3;              // warpgroup: K quarter (0..3)
    const int wl = wid & 7;
    const int wm = wl & 3, wn = wl >> 2;
    const int g = lane >> 2, tg = lane & 3;
    const int n0 = blockIdx.x * 32;
    const int bid = blockIdx.x;

    // ---- build fragment-packed W_h slice in SMEM (once) ----
#pragma unroll 4
    for (int e = tid; e < 8192; e += 1024) {
        int lane_e = e & 31, wn_e = (e >> 5) & 1, k8 = e >> 6;
        int ge = lane_e >> 2, tge = lane_e & 3;
        const float* w0 = g_WhT + (size_t)(n0 + wn_e * 16 + ge) * 1024 + k8 * 8 + tge;
        float4 v;
        v.x = w0[0];
        v.y = w0[4];
        v.z = w0[8 * 1024];
        v.w = w0[8 * 1024 + 4];
        *(float4*)(Bf + (size_t)e * 4) = v;
    }

    // ---- cell state in registers (threads 0..511 own the 512 items) ----
    const int eb = tid >> 3, eu = tid & 7;           // elementwise (b, unit)
    float creg = 0.f;
    if (tid < 512) creg = g_c[(size_t)eb * 1024 + (n0 >> 2) + eu];

    // ---- barrier base: all flags equal at launch start (monotonic) ----
    __shared__ unsigned sh_base;
    if (tid == 0) sh_base = ldacq(&g_flags[bid * 32]);
    __syncthreads();
    const unsigned base = sh_base;

    // per-warp fragment base: Bf + (k8*2 + wn)*32 + lane  (float4 units)
    const float4* bfw = (const float4*)Bf + wn * 32 + lane;
    const int k8off = wg * 32;                        // wg's K quarter in k8 units

    for (int t = 0; t < 512; t++) {
        const float* hin  = (t == 0) ? g_h0 : g_Hall + (size_t)(t - 1) * 64 * 1024;
        float* hall       = g_Hall + (size_t)t * 64 * 1024;
        const float* gpre = g_Gpre + (size_t)t * 64 * 4096;

        // stage loads all 4 K quarters: 1024 float4 / 1024 thr = 1 each
        auto issueA = [&](int stg, int kb) {     // kb = kbi*16
            float* as = Ast + stg * AST_STAGE;
            int c4 = tid & 3, rw = tid >> 2;
            int wgq = rw >> 6, row = rw & 63;
            cpa16(&as[wgq * AST_Q + row * 20 + c4 * 4],
                  hin + (size_t)row * 1024 + wgq * 256 + kb + c4 * 4);
        };

        float acc[2][4];
#pragma unroll
        for (int i = 0; i < 2; i++)
#pragma unroll
            for (int k = 0; k < 4; k++) acc[i][k] = 0.f;

        // prefill: Gs (1 float4 for tid<512) + stage0 in one group, then 1,2
        if (tid < 512) {
            int row = tid >> 3, c4 = tid & 7;
            cpa16(&Gs[row * 32 + c4 * 4],
                  gpre + (size_t)row * 4096 + n0 + c4 * 4);
        }
        issueA(0, 0);  cp_commit();
        issueA(1, 16); cp_commit();
        issueA(2, 32); cp_commit();

        for (int kbi = 0; kbi < 16; kbi++) {
            cp_wait<2>();
            __syncthreads();
            const uint32_t* as = (const uint32_t*)(Ast + (kbi & 3) * AST_STAGE
                                                   + wg * AST_Q);
#pragma unroll
            for (int kk = 0; kk < 16; kk += 8) {
                int k8 = k8off + kbi * 2 + (kk >> 3);
                uint32_t a[4];
                int r0 = wm * 16 + g;
                a[0] = as[r0 * 20 + kk + tg];
                a[1] = as[(r0 + 8) * 20 + kk + tg];
                a[2] = as[r0 * 20 + kk + 4 + tg];
                a[3] = as[(r0 + 8) * 20 + kk + 4 + tg];
                float4 bv = bfw[k8 * 64];
                uint32_t b0[2] = { __float_as_uint(bv.x), __float_as_uint(bv.y) };
                uint32_t b1[2] = { __float_as_uint(bv.z), __float_as_uint(bv.w) };
                mma_tf32(acc[0], a, b0);
                mma_tf32(acc[1], a, b1);
            }
            if (kbi + 3 < 16) issueA((kbi + 3) & 3, (kbi + 3) * 16);
            cp_commit();                 // one commit per iteration, always
        }

        // ---- gate exchange: each wg writes its partial [4][64][36] ----
        cp_wait<0>();
        __syncthreads();
        float* gb = Ast;                  // alias: [4 wg][64][36], cols 0..31
        float* gbw = gb + wg * 2304;
#pragma unroll
        for (int nt = 0; nt < 2; nt++) {
            int row = wm * 16 + g, col = wn * 16 + nt * 8 + 2 * tg;
            gbw[row * 36 + col]           = acc[nt][0];
            gbw[row * 36 + col + 1]       = acc[nt][1];
            gbw[(row + 8) * 36 + col]     = acc[nt][2];
            gbw[(row + 8) * 36 + col + 1] = acc[nt][3];
        }
        __syncthreads();

        // ---- fused LSTM elementwise: 512 items, threads 0..511 ----
        if (tid < 512) {
            int cl = 4 * eu;
            int o = eb * 36 + cl;
            float gf = Gs[eb * 32 + cl]     + gb[o]          + gb[2304 + o]
                     + gb[4608 + o]         + gb[6912 + o];
            float gi = Gs[eb * 32 + cl + 1] + gb[o + 1]      + gb[2304 + o + 1]
                     + gb[4608 + o + 1]     + gb[6912 + o + 1];
            float gc = Gs[eb * 32 + cl + 2] + gb[o + 2]      + gb[2304 + o + 2]
                     + gb[4608 + o + 2]     + gb[6912 + o + 2];
            float go = Gs[eb * 32 + cl + 3] + gb[o + 3]      + gb[2304 + o + 3]
                     + gb[4608 + o + 3]     + gb[6912 + o + 3];
            float f  = sigm(gf);
            float i  = sigm(gi);
            float ch = tanh_f(gc);
            float oo = sigm(go);
            float cn = f * creg + i * ch;
            creg = cn;
            float hr = tf32r(oo * tanh_f(cn));
            hall[(size_t)eb * 1024 + (n0 >> 2) + eu] = hr;
        }

        // ---- flat all-poll grid barrier (monotonic flags) ----
        const unsigned target = base + (unsigned)t + 1u;
        __syncthreads();                            // all h writes done
        if (tid == 0) strel(&g_flags[bid * 32], target);
        if (tid < 128) {
            while ((int)(ldacq(&g_flags[tid * 32]) - target) < 0) __nanosleep(32);
        }
        __syncthreads();                            // all threads see new h
    }
}

// ---------------- launch -----------------------------------------------------
extern "C" void kernel_launch(void* const* d_in, const int* in_sizes, int n_in,
                              void* d_out, int out_size) {
    const float* x    = (const float*)d_in[0];
    const float* h0   = (const float*)d_in[1];
    const float* c0   = (const float*)d_in[2];
    const float* W_f  = (const float*)d_in[3];
    const float* b_f  = (const float*)d_in[4];
    const float* W_i  = (const float*)d_in[5];
    const float* b_i  = (const float*)d_in[6];
    const float* W_c  = (const float*)d_in[7];
    const float* b_c  = (const float*)d_in[8];
    const float* W_o  = (const float*)d_in[9];
    const float* b_o  = (const float*)d_in[10];
    const float* W_out = (const float*)d_in[11];
    const float* b_out = (const float*)d_in[12];
    float* out = (float*)d_out;

    cudaFuncSetAttribute(k_gemm, cudaFuncAttributeMaxDynamicSharedMemorySize, GEMM_SMEM);
    cudaFuncSetAttribute(k_rec,  cudaFuncAttributeMaxDynamicSharedMemorySize, REC_SMEM);

    // 5 launches; slot 4 = k_rec (ncu -s 5 -c 1 profiles the 4th launch).
    k_prepA<<<33024, 256>>>(x, b_f, b_i, b_c, b_o, h0, c0);
    k_prepB<<<9216, dim3(32, 8)>>>(W_f, W_i, W_c, W_o, W_out);

    // pre-GEMM: G_pre (M=32768, N=4096), 8192 CTAs supertiled
    k_gemm<<<8192, 256, GEMM_SMEM>>>(nullptr, nullptr, 0);

    // persistent recurrence: all 512 steps in one kernel
    k_rec<<<128, 1024, REC_SMEM>>>();

    // post-GEMM: out (M=32768, N=1024), 2048 CTAs supertiled
    k_gemm<<<2048, 256, GEMM_SMEM>>>(out, b_out, 1);
}

// round 13
// speedup vs baseline: 1.0229x; 1.0229x over previous
#include <cuda_runtime.h>
#include <cstdint>
#include <math.h>

// ---------------------------------------------------------------------------
// LSTM  B=64 S=512 D=1024 H=1024 F=1024
//  1) G_pre = Xt @ WxT^T + b_g      (tf32 GEMM, M=32768 N=4096 K=1024)
//  2) ONE persistent kernel, 128 CTAs x 512 thr, 512 steps:
//       gates = G_pre[t] + h@WhT^T ; fused LSTM elementwise
//     Split-K x2: warpgroup wg does K[wg*512,(wg+1)*512) with a PRIVATE
//     4-stage cp.async ring + wg-scoped named barriers (no cross-wg coupling
//     in the mainloop). W_h fragment-packed in SMEM; c in registers;
//     flat all-poll grid barrier.
//  3) out = Hall @ WoT^T + b_out    (tf32 GEMM, M=32768 N=1024 K=1024)
// Big GEMMs: 4-stage ring, issue-before-compute (3 groups in flight).
// Gate columns interleaved: n = 4*unit + gate.
// ---------------------------------------------------------------------------

#define DEVINL __device__ __forceinline__

// ---------------- static device scratch (no runtime allocation) ------------
__device__ float g_Xt  [(size_t)32768 * 1024];   // x as (t,b) rows, tf32-rounded
__device__ float g_Gpre[(size_t)32768 * 4096];   // x-part of gates (+bias)
__device__ float g_Hall[(size_t)32768 * 1024];   // all h_t, tf32-rounded
__device__ float g_WxT [(size_t)4096 * 1024];    // [n][k] interleaved, x rows
__device__ float g_WhT [(size_t)4096 * 1024];    // [n][k] interleaved, h rows
__device__ float g_WoT [(size_t)1024 * 1024];    // W_out^T [f][h]
__device__ float g_bg  [4096];                   // gate bias, interleaved
__device__ float g_h0  [64 * 1024];              // initial h (tf32-rounded)
__device__ float g_c   [64 * 1024];              // cell state (init only)

// grid-barrier state: monotonic counters (never reset; base read per launch)
__device__ unsigned g_flags[128 * 32];           // flag i at [i*32] (own 128B line)

// ---------------- helpers ---------------------------------------------------
DEVINL uint32_t f2tf32(float x) {
    uint32_t r; asm("cvt.rna.tf32.f32 %0, %1;" : "=r"(r) : "f"(x)); return r;
}
DEVINL float tf32r(float x) { return __uint_as_float(f2tf32(x)); }

DEVINL void cpa16(void* dst, const void* src) {
    uint32_t d = (uint32_t)__cvta_generic_to_shared(dst);
    asm volatile("cp.async.cg.shared.global [%0], [%1], 16;\n" :: "r"(d), "l"(src));
}
DEVINL void cp_commit() { asm volatile("cp.async.commit_group;\n"); }
template <int N> DEVINL void cp_wait() { asm volatile("cp.async.wait_group %0;\n" :: "n"(N)); }

DEVINL void barw(int id) {               // wg-scoped named barrier, 256 thr
    asm volatile("bar.sync %0, 256;" :: "r"(id) : "memory");
}

DEVINL void mma_tf32(float* c, const uint32_t* a, const uint32_t* b) {
    asm volatile(
        "mma.sync.aligned.m16n8k8.row.col.f32.tf32.tf32.f32 "
        "{%0,%1,%2,%3},{%4,%5,%6,%7},{%8,%9},{%0,%1,%2,%3};\n"
        : "+f"(c[0]), "+f"(c[1]), "+f"(c[2]), "+f"(c[3])
        : "r"(a[0]), "r"(a[1]), "r"(a[2]), "r"(a[3]), "r"(b[0]), "r"(b[1]));
}
DEVINL float sigm(float x)   { return 1.f / (1.f + __expf(-x)); }
DEVINL float tanh_f(float x) { return 2.f / (1.f + __expf(-2.f * x)) - 1.f; }

DEVINL unsigned ldacq(const unsigned* p) {
    unsigned v; asm volatile("ld.acquire.gpu.global.u32 %0, [%1];" : "=r"(v) : "l"(p)); return v;
}
DEVINL void strel(unsigned* p, unsigned v) {
    asm volatile("st.release.gpu.global.u32 [%0], %1;" :: "l"(p), "r"(v));
}

// ---------------- prepA: x transform + bias/state init ----------------------
__global__ void __launch_bounds__(256) k_prepA(
        const float* __restrict__ x,
        const float* __restrict__ bf, const float* __restrict__ bi,
        const float* __restrict__ bc, const float* __restrict__ bo,
        const float* __restrict__ h0, const float* __restrict__ c0) {
    if (blockIdx.x < 32768) {
        size_t p = (size_t)blockIdx.x * 256 + threadIdx.x;
        int d4 = (int)(p & 255);
        size_t m = p >> 8;
        int b = (int)(m & 63), t = (int)(m >> 6);
        float4 v = *(const float4*)(x + ((size_t)b * 512 + t) * 1024 + (size_t)d4 * 4);
        v.x = tf32r(v.x); v.y = tf32r(v.y); v.z = tf32r(v.z); v.w = tf32r(v.w);
        *(float4*)(g_Xt + m * 1024 + (size_t)d4 * 4) = v;
    } else {
        int i = (blockIdx.x - 32768) * 256 + threadIdx.x;   // 0..65535
        if (i < 4096) {
            int u = i >> 2, gt = i & 3;
            const float* b = (gt == 0) ? bf : (gt == 1) ? bi : (gt == 2) ? bc : bo;
            g_bg[i] = b[u];
        }
        g_h0[i] = tf32r(h0[i]);
        g_c[i]  = c0[i];
    }
}

// ---------------- prepB: weight transposes ----------------------------------
__global__ void k_prepB(const float* __restrict__ Wf, const float* __restrict__ Wi,
                        const float* __restrict__ Wc, const float* __restrict__ Wo,
                        const float* __restrict__ Wout) {
    __shared__ float tile[32][33];
    int tx = threadIdx.x, ty = threadIdx.y;
    if (blockIdx.x < 8192) {
        int bid = blockIdx.x;
        int s    = bid >> 12;         // 0 = x rows, 1 = h rows
        int gate = (bid >> 10) & 3;
        int kt   = (bid >> 5) & 31;
        int ut   = bid & 31;
        const float* W = (gate == 0) ? Wf : (gate == 1) ? Wi : (gate == 2) ? Wc : Wo;
#pragma unroll
        for (int r = 0; r < 4; r++) {
            int k = kt * 32 + ty + r * 8;
            tile[ty + r * 8][tx] = W[(size_t)(s * 1024 + k) * 1024 + ut * 32 + tx];
        }
        __syncthreads();
        float* WT = s ? g_WhT : g_WxT;
#pragma unroll
        for (int r = 0; r < 4; r++) {
            int ul = ty + r * 8;
            int n = 4 * (ut * 32 + ul) + gate;
            WT[(size_t)n * 1024 + kt * 32 + tx] = tf32r(tile[tx][ul]);
        }
    } else {
        int bid = blockIdx.x - 8192;
        int ft = bid & 31, ht = bid >> 5;
#pragma unroll
        for (int r = 0; r < 4; r++) {
            int h = ht * 32 + ty + r * 8;
            tile[ty + r * 8][tx] = Wout[(size_t)h * 1024 + ft * 32 + tx];
        }
        __syncthreads();
#pragma unroll
        for (int r = 0; r < 4; r++) {
            int fl = ty + r * 8;
            int f = ft * 32 + fl;
            g_WoT[(size_t)f * 1024 + ht * 32 + tx] = tf32r(tile[tx][fl]);
        }
    }
}

// ---------------- big tf32 GEMM: BM=128 BN=128 BK=32, 256 thr, 4-stage -----
// issue-before-compute: 3 cp.async groups in flight during every compute.
static const int GEMM_SMEM = 4 * 2 * 128 * 36 * 4;   // 147456 B

__global__ void __launch_bounds__(256) k_gemm(float* __restrict__ Cpost,
                                              const float* __restrict__ bias_post,
                                              int mode) {
    extern __shared__ float sm[];
    const float* A  = mode ? g_Hall : g_Xt;
    const float* BT = mode ? g_WoT  : g_WxT;
    float* As = sm;                    // [4][128][36]
    float* Bs = sm + 4 * 128 * 36;     // [4][128][36]

    const int tid = threadIdx.x, lane = tid & 31, wid = tid >> 5;
    const int wm = wid & 1, wn = wid >> 1;          // 2 x 4 warps
    const int g = lane >> 2, tg = lane & 3;

    int mi, ni;
    if (mode == 0) {                     // 32 n-blocks
        int sup = blockIdx.x >> 8, rem = blockIdx.x & 255;
        mi = sup * 8 + (rem & 7); ni = rem >> 3;
    } else {                             // 8 n-blocks
        int sup = blockIdx.x >> 6, rem = blockIdx.x & 63;
        mi = sup * 8 + (rem & 7); ni = rem >> 3;
    }
    const int m0 = mi * 128;
    const int n0 = ni * 128;

    float acc[4][4][4];
#pragma unroll
    for (int i = 0; i < 4; i++)
#pragma unroll
        for (int j = 0; j < 4; j++)
#pragma unroll
            for (int k = 0; k < 4; k++) acc[i][j][k] = 0.f;

    auto issue = [&](int stg, int kb) {
        float* as = As + stg * 128 * 36;
        float* bs = Bs + stg * 128 * 36;
#pragma unroll
        for (int r = 0; r < 4; r++) {
            int f = tid + r * 256; int row = f >> 3, c4 = f & 7;
            cpa16(&as[row * 36 + c4 * 4],
                  A + (size_t)(m0 + row) * 1024 + kb + c4 * 4);
        }
#pragma unroll
        for (int r = 0; r < 4; r++) {
            int f = tid + r * 256; int row = f >> 3, c4 = f & 7;
            cpa16(&bs[row * 36 + c4 * 4],
                  BT + (size_t)(n0 + row) * 1024 + kb + c4 * 4);
        }
    };

    issue(0, 0);  cp_commit();
    issue(1, 32); cp_commit();
    issue(2, 64); cp_commit();

    for (int kbi = 0; kbi < 32; kbi++) {
        cp_wait<2>();                    // stage kbi landed
        __syncthreads();                 // all warps done with stage (kbi+3)&3
        if (kbi + 3 < 32) issue((kbi + 3) & 3, (kbi + 3) * 32);
        cp_commit();                     // uniform group count
        const uint32_t* as = (const uint32_t*)(As + (kbi & 3) * 128 * 36);
        const uint32_t* bs = (const uint32_t*)(Bs + (kbi & 3) * 128 * 36);
#pragma unroll
        for (int kk = 0; kk < 32; kk += 8) {
            uint32_t a[4][4], b[4][2];
#pragma unroll
            for (int mt = 0; mt < 4; mt++) {
                int r0 = wm * 64 + mt * 16 + g;
                a[mt][0] = as[r0 * 36 + kk + tg];
                a[mt][1] = as[(r0 + 8) * 36 + kk + tg];
                a[mt][2] = as[r0 * 36 + kk + 4 + tg];
                a[mt][3] = as[(r0 + 8) * 36 + kk + 4 + tg];
            }
#pragma unroll
            for (int nt = 0; nt < 4; nt++) {
                int nr = wn * 32 + nt * 8 + g;
                b[nt][0] = bs[nr * 36 + kk + tg];
                b[nt][1] = bs[nr * 36 + kk + 4 + tg];
            }
#pragma unroll
            for (int mt = 0; mt < 4; mt++)
#pragma unroll
                for (int nt = 0; nt < 4; nt++) mma_tf32(acc[mt][nt], a[mt], b[nt]);
        }
    }

    // epilogue
#pragma unroll
    for (int mt = 0; mt < 4; mt++) {
#pragma unroll
        for (int nt = 0; nt < 4; nt++) {
            int row = m0 + wm * 64 + mt * 16 + g;
            int col = n0 + wn * 32 + nt * 8 + 2 * tg;
#pragma unroll
            for (int h = 0; h < 2; h++) {
                int gr = row + h * 8;
                float b0, b1;
                float v0 = acc[mt][nt][h * 2 + 0];
                float v1 = acc[mt][nt][h * 2 + 1];
                if (mode == 0) { b0 = g_bg[col]; b1 = g_bg[col + 1]; }
                else           { b0 = bias_post[col]; b1 = bias_post[col + 1]; }
                float2 v = make_float2(v0 + b0, v1 + b1);
                if (mode == 0) {
                    *(float2*)(g_Gpre + (size_t)gr * 4096 + col) = v;
                } else {
                    size_t o = ((size_t)(gr & 63) * 512 + (gr >> 6)) * 1024 + col;
                    *(float2*)(Cpost + o) = v;
                }
            }
        }
    }
}

// ---------------- persistent recurrence: 128 CTAs x 512 thr, 512 steps -----
// CTA owns gate columns [n0, n0+32) = units [n0/4, n0/4+8).
// Split-K x2: warpgroup wg (= wid>>3) computes K[wg*512,(wg+1)*512) with a
// PRIVATE 4-stage ring + named barrier (1+wg, 256). SMEM:
//   Bf (fragment-packed W_h, 128KB) | Ast [2 wg][4 stg][64][36] | Gs [64][32]
static const int AST_S    = 64 * 36;                  // 2304 floats per stage
static const int AST_WG   = 4 * AST_S;                // 9216 floats per wg
static const int REC_SMEM = (32768 + 2 * AST_WG + 2048) * 4;   // 212992 B

__global__ void __launch_bounds__(512) k_rec() {
    extern __shared__ float smr[];
    float* Bf  = smr;                     // [128 k8][2 wn][32 lane][4] = 128KB
    float* Ast = smr + 32768;             // [2][4][64][36]; aliased as gb
    float* Gs  = smr + 32768 + 2 * AST_WG;   // [64][32] Gpre tile

    const int tid = threadIdx.x, lane = tid & 31, wid = tid >> 5;
    const int wg = wid >> 3;              // warpgroup: K half
    const int wl = wid & 7;
    const int wm = wl & 3, wn = wl >> 2;
    const int g = lane >> 2, tg = lane & 3;
    const int n0 = blockIdx.x * 32;
    const int bid = blockIdx.x;
    const int t256 = tid & 255;           // index within warpgroup

    // ---- build fragment-packed W_h slice in SMEM (once) ----
#pragma unroll 4
    for (int e = tid; e < 8192; e += 512) {
        int lane_e = e & 31, wn_e = (e >> 5) & 1, k8 = e >> 6;
        int ge = lane_e >> 2, tge = lane_e & 3;
        const float* w0 = g_WhT + (size_t)(n0 + wn_e * 16 + ge) * 1024 + k8 * 8 + tge;
        float4 v;
        v.x = w0[0];
        v.y = w0[4];
        v.z = w0[8 * 1024];
        v.w = w0[8 * 1024 + 4];
        *(float4*)(Bf + (size_t)e * 4) = v;
    }

    // ---- cell state in registers (1 item/thread) ----
    const int eb = tid >> 3, eu = tid & 7;           // elementwise (b, unit)
    float creg = g_c[(size_t)eb * 1024 + (n0 >> 2) + eu];

    // ---- barrier base: all flags equal at launch start (monotonic) ----
    __shared__ unsigned sh_base;
    if (tid == 0) sh_base = ldacq(&g_flags[bid * 32]);
    __syncthreads();
    const unsigned base = sh_base;

    // per-warp fragment base: Bf + (k8*2 + wn)*32 + lane  (float4 units)
    const float4* bfw = (const float4*)Bf + wn * 32 + lane;
    const int k8off = wg * 64;            // wg's K half in k8 units
    float* AstW = Ast + wg * AST_WG;      // wg-private stage ring

    for (int t = 0; t < 512; t++) {
        const float* hin  = (t == 0) ? g_h0 : g_Hall + (size_t)(t - 1) * 64 * 1024;
        float* hall       = g_Hall + (size_t)t * 64 * 1024;
        const float* gpre = g_Gpre + (size_t)t * 64 * 4096;

        // wg-private stage load: 64 rows x 32 cols of wg's K-half
        auto issueA = [&](int stg, int kb) {     // kb in [0,512)
            float* as = AstW + stg * AST_S;
#pragma unroll
            for (int r = 0; r < 2; r++) {
                int f = t256 + r * 256; int row = f >> 3, c4 = f & 7;
                cpa16(&as[row * 36 + c4 * 4],
                      hin + (size_t)row * 1024 + wg * 512 + kb + c4 * 4);
            }
        };

        float acc[2][4];
#pragma unroll
        for (int i = 0; i < 2; i++)
#pragma unroll
            for (int k = 0; k < 4; k++) acc[i][k] = 0.f;

        // prefill: Gs (1 float4/thread) rides with stage0; then stages 1,2
        {
            int row = tid >> 3, c4 = tid & 7;
            cpa16(&Gs[row * 32 + c4 * 4],
                  gpre + (size_t)row * 4096 + n0 + c4 * 4);
        }
        issueA(0, 0);  cp_commit();
        issueA(1, 32); cp_commit();
        issueA(2, 64); cp_commit();

        for (int kbi = 0; kbi < 16; kbi++) {
            cp_wait<2>();                 // stage kbi landed
            barw(1 + wg);                 // wg-scoped: publish + WAR protect
            if (kbi + 3 < 16) issueA((kbi + 3) & 3, (kbi + 3) * 32);
            cp_commit();
            const uint32_t* as = (const uint32_t*)(AstW + (kbi & 3) * AST_S);
#pragma unroll
            for (int kk = 0; kk < 32; kk += 8) {
                int k8 = k8off + kbi * 4 + (kk >> 3);
                uint32_t a[4];
                int r0 = wm * 16 + g;
                a[0] = as[r0 * 36 + kk + tg];
                a[1] = as[(r0 + 8) * 36 + kk + tg];
                a[2] = as[r0 * 36 + kk + 4 + tg];
                a[3] = as[(r0 + 8) * 36 + kk + 4 + tg];
                float4 bv = bfw[k8 * 64];
                uint32_t b0[2] = { __float_as_uint(bv.x), __float_as_uint(bv.y) };
                uint32_t b1[2] = { __float_as_uint(bv.z), __float_as_uint(bv.w) };
                mma_tf32(acc[0], a, b0);
                mma_tf32(acc[1], a, b1);
            }
        }

        // ---- gate exchange: each wg writes its partial into its region ----
        cp_wait<0>();
        __syncthreads();                  // cross-wg: all compute done
        float* gb = Ast;                  // alias: [wg][64][36] at wg*AST_WG
        float* gbw = Ast + wg * AST_WG;
#pragma unroll
        for (int nt = 0; nt < 2; nt++) {
            int row = wm * 16 + g, col = wn * 16 + nt * 8 + 2 * tg;
            gbw[row * 36 + col]           = acc[nt][0];
            gbw[row * 36 + col + 1]       = acc[nt][1];
            gbw[(row + 8) * 36 + col]     = acc[nt][2];
            gbw[(row + 8) * 36 + col + 1] = acc[nt][3];
        }
        __syncthreads();

        // ---- fused LSTM elementwise: 512 items, 1 per thread ----
        {
            int cl = 4 * eu;
            int o = eb * 36 + cl;
            float gf = Gs[eb * 32 + cl]     + gb[o]     + gb[AST_WG + o];
            float gi = Gs[eb * 32 + cl + 1] + gb[o + 1] + gb[AST_WG + o + 1];
            float gc = Gs[eb * 32 + cl + 2] + gb[o + 2] + gb[AST_WG + o + 2];
            float go = Gs[eb * 32 + cl + 3] + gb[o + 3] + gb[AST_WG + o + 3];
            float f  = sigm(gf);
            float i  = sigm(gi);
            float ch = tanh_f(gc);
            float oo = sigm(go);
            float cn = f * creg + i * ch;
            creg = cn;
            float hr = tf32r(oo * tanh_f(cn));
            hall[(size_t)eb * 1024 + (n0 >> 2) + eu] = hr;
        }

        // ---- flat all-poll grid barrier (monotonic flags) ----
        const unsigned target = base + (unsigned)t + 1u;
        __syncthreads();                            // all h writes done
        if (tid == 0) strel(&g_flags[bid * 32], target);
        if (tid < 128) {
            while ((int)(ldacq(&g_flags[tid * 32]) - target) < 0) __nanosleep(32);
        }
        __syncthreads();                            // all threads see new h
    }
}

// ---------------- launch -----------------------------------------------------
extern "C" void kernel_launch(void* const* d_in, const int* in_sizes, int n_in,
                              void* d_out, int out_size) {
    const float* x    = (const float*)d_in[0];
    const float* h0   = (const float*)d_in[1];
    const float* c0   = (const float*)d_in[2];
    const float* W_f  = (const float*)d_in[3];
    const float* b_f  = (const float*)d_in[4];
    const float* W_i  = (const float*)d_in[5];
    const float* b_i  = (const float*)d_in[6];
    const float* W_c  = (const float*)d_in[7];
    const float* b_c  = (const float*)d_in[8];
    const float* W_o  = (const float*)d_in[9];
    const float* b_o  = (const float*)d_in[10];
    const float* W_out = (const float*)d_in[11];
    const float* b_out = (const float*)d_in[12];
    float* out = (float*)d_out;

    cudaFuncSetAttribute(k_gemm, cudaFuncAttributeMaxDynamicSharedMemorySize, GEMM_SMEM);
    cudaFuncSetAttribute(k_rec,  cudaFuncAttributeMaxDynamicSharedMemorySize, REC_SMEM);

    // 5 launches; slot 4 = k_rec (ncu -s 5 -c 1 profiles the 4th launch).
    k_prepA<<<33024, 256>>>(x, b_f, b_i, b_c, b_o, h0, c0);
    k_prepB<<<9216, dim3(32, 8)>>>(W_f, W_i, W_c, W_o, W_out);

    // pre-GEMM: G_pre (M=32768, N=4096), 8192 CTAs supertiled
    k_gemm<<<8192, 256, GEMM_SMEM>>>(nullptr, nullptr, 0);

    // persistent recurrence: all 512 steps in one kernel
    k_rec<<<128, 512, REC_SMEM>>>();

    // post-GEMM: out (M=32768, N=1024), 2048 CTAs supertiled
    k_gemm<<<2048, 256, GEMM_SMEM>>>(out, b_out, 1);
}

// round 14
// speedup vs baseline: 1.0232x; 1.0003x over previous
#include <cuda_runtime.h>
#include <cstdint>
#include <math.h>

// ---------------------------------------------------------------------------
// LSTM  B=64 S=512 D=1024 H=1024 F=1024
//  1) G_pre = Xt @ WxT^T + b_g      (tf32 GEMM, M=32768 N=4096 K=1024)
//  2) ONE persistent kernel, 128 CTAs x 512 thr, 512 steps (R11 config):
//       gates = G_pre[t] + h@WhT^T ; fused LSTM elementwise
//     Split-K x2 across warpgroups; shared 3-stage cp.async pipeline;
//     W_h fragment-packed in SMEM; c in registers; flat all-poll barrier.
//  3) out = Hall @ WoT^T + b_out    (tf32 GEMM, M=32768 N=1024 K=1024)
// Big GEMMs: 4-stage ring, issue-before-compute (3 groups in flight).
// Launch order: prepA, prep_w, prep_wout, gemm_pre(<- ncu slot), rec, gemm.
// ---------------------------------------------------------------------------

#define DEVINL __device__ __forceinline__

// ---------------- static device scratch (no runtime allocation) ------------
__device__ float g_Xt  [(size_t)32768 * 1024];   // x as (t,b) rows, tf32-rounded
__device__ float g_Gpre[(size_t)32768 * 4096];   // x-part of gates (+bias)
__device__ float g_Hall[(size_t)32768 * 1024];   // all h_t, tf32-rounded
__device__ float g_WxT [(size_t)4096 * 1024];    // [n][k] interleaved, x rows
__device__ float g_WhT [(size_t)4096 * 1024];    // [n][k] interleaved, h rows
__device__ float g_WoT [(size_t)1024 * 1024];    // W_out^T [f][h]
__device__ float g_bg  [4096];                   // gate bias, interleaved
__device__ float g_h0  [64 * 1024];              // initial h (tf32-rounded)
__device__ float g_c   [64 * 1024];              // cell state (init only)

// grid-barrier state: monotonic counters (never reset; base read per launch)
__device__ unsigned g_flags[128 * 32];           // flag i at [i*32] (own 128B line)

// ---------------- helpers ---------------------------------------------------
DEVINL uint32_t f2tf32(float x) {
    uint32_t r; asm("cvt.rna.tf32.f32 %0, %1;" : "=r"(r) : "f"(x)); return r;
}
DEVINL float tf32r(float x) { return __uint_as_float(f2tf32(x)); }

DEVINL void cpa16(void* dst, const void* src) {
    uint32_t d = (uint32_t)__cvta_generic_to_shared(dst);
    asm volatile("cp.async.cg.shared.global [%0], [%1], 16;\n" :: "r"(d), "l"(src));
}
DEVINL void cp_commit() { asm volatile("cp.async.commit_group;\n"); }
template <int N> DEVINL void cp_wait() { asm volatile("cp.async.wait_group %0;\n" :: "n"(N)); }

DEVINL void mma_tf32(float* c, const uint32_t* a, const uint32_t* b) {
    asm volatile(
        "mma.sync.aligned.m16n8k8.row.col.f32.tf32.tf32.f32 "
        "{%0,%1,%2,%3},{%4,%5,%6,%7},{%8,%9},{%0,%1,%2,%3};\n"
        : "+f"(c[0]), "+f"(c[1]), "+f"(c[2]), "+f"(c[3])
        : "r"(a[0]), "r"(a[1]), "r"(a[2]), "r"(a[3]), "r"(b[0]), "r"(b[1]));
}
DEVINL float sigm(float x)   { return 1.f / (1.f + __expf(-x)); }
DEVINL float tanh_f(float x) { return 2.f / (1.f + __expf(-2.f * x)) - 1.f; }

DEVINL unsigned ldacq(const unsigned* p) {
    unsigned v; asm volatile("ld.acquire.gpu.global.u32 %0, [%1];" : "=r"(v) : "l"(p)); return v;
}
DEVINL void strel(unsigned* p, unsigned v) {
    asm volatile("st.release.gpu.global.u32 [%0], %1;" :: "l"(p), "r"(v));
}

// ---------------- prepA: x transform + bias/state init ----------------------
__global__ void __launch_bounds__(256) k_prepA(
        const float* __restrict__ x,
        const float* __restrict__ bf, const float* __restrict__ bi,
        const float* __restrict__ bc, const float* __restrict__ bo,
        const float* __restrict__ h0, const float* __restrict__ c0) {
    if (blockIdx.x < 32768) {
        size_t p = (size_t)blockIdx.x * 256 + threadIdx.x;
        int d4 = (int)(p & 255);
        size_t m = p >> 8;
        int b = (int)(m & 63), t = (int)(m >> 6);
        float4 v = *(const float4*)(x + ((size_t)b * 512 + t) * 1024 + (size_t)d4 * 4);
        v.x = tf32r(v.x); v.y = tf32r(v.y); v.z = tf32r(v.z); v.w = tf32r(v.w);
        *(float4*)(g_Xt + m * 1024 + (size_t)d4 * 4) = v;
    } else {
        int i = (blockIdx.x - 32768) * 256 + threadIdx.x;   // 0..65535
        if (i < 4096) {
            int u = i >> 2, gt = i & 3;
            const float* b = (gt == 0) ? bf : (gt == 1) ? bi : (gt == 2) ? bc : bo;
            g_bg[i] = b[u];
        }
        g_h0[i] = tf32r(h0[i]);
        g_c[i]  = c0[i];
    }
}

// ---------------- prep_w: gate weight transposes -----------------------------
__global__ void k_prep_w(const float* __restrict__ Wf, const float* __restrict__ Wi,
                         const float* __restrict__ Wc, const float* __restrict__ Wo) {
    __shared__ float tile[32][33];
    int tx = threadIdx.x, ty = threadIdx.y;
    int bid = blockIdx.x;
    int s    = bid >> 12;         // 0 = x rows, 1 = h rows
    int gate = (bid >> 10) & 3;
    int kt   = (bid >> 5) & 31;
    int ut   = bid & 31;
    const float* W = (gate == 0) ? Wf : (gate == 1) ? Wi : (gate == 2) ? Wc : Wo;
#pragma unroll
    for (int r = 0; r < 4; r++) {
        int k = kt * 32 + ty + r * 8;
        tile[ty + r * 8][tx] = W[(size_t)(s * 1024 + k) * 1024 + ut * 32 + tx];
    }
    __syncthreads();
    float* WT = s ? g_WhT : g_WxT;
#pragma unroll
    for (int r = 0; r < 4; r++) {
        int ul = ty + r * 8;
        int n = 4 * (ut * 32 + ul) + gate;
        WT[(size_t)n * 1024 + kt * 32 + tx] = tf32r(tile[tx][ul]);
    }
}

// ---------------- prep_wout: W_out transpose ----------------------------------
__global__ void k_prep_wout(const float* __restrict__ Wout) {
    __shared__ float tile[32][33];
    int tx = threadIdx.x, ty = threadIdx.y;
    int ft = blockIdx.x & 31, ht = blockIdx.x >> 5;
#pragma unroll
    for (int r = 0; r < 4; r++) {
        int h = ht * 32 + ty + r * 8;
        tile[ty + r * 8][tx] = Wout[(size_t)h * 1024 + ft * 32 + tx];
    }
    __syncthreads();
#pragma unroll
    for (int r = 0; r < 4; r++) {
        int fl = ty + r * 8;
        int f = ft * 32 + fl;
        g_WoT[(size_t)f * 1024 + ht * 32 + tx] = tf32r(tile[tx][fl]);
    }
}

// ---------------- big tf32 GEMM: BM=128 BN=128 BK=32, 256 thr, 4-stage -----
// issue-before-compute: 3 cp.async groups in flight during every compute.
static const int GEMM_SMEM = 4 * 2 * 128 * 36 * 4;   // 147456 B

__global__ void __launch_bounds__(256) k_gemm(float* __restrict__ Cpost,
                                              const float* __restrict__ bias_post,
                                              int mode) {
    extern __shared__ float sm[];
    const float* A  = mode ? g_Hall : g_Xt;
    const float* BT = mode ? g_WoT  : g_WxT;
    float* As = sm;                    // [4][128][36]
    float* Bs = sm + 4 * 128 * 36;     // [4][128][36]

    const int tid = threadIdx.x, lane = tid & 31, wid = tid >> 5;
    const int wm = wid & 1, wn = wid >> 1;          // 2 x 4 warps
    const int g = lane >> 2, tg = lane & 3;

    int mi, ni;
    if (mode == 0) {                     // 32 n-blocks
        int sup = blockIdx.x >> 8, rem = blockIdx.x & 255;
        mi = sup * 8 + (rem & 7); ni = rem >> 3;
    } else {                             // 8 n-blocks
        int sup = blockIdx.x >> 6, rem = blockIdx.x & 63;
        mi = sup * 8 + (rem & 7); ni = rem >> 3;
    }
    const int m0 = mi * 128;
    const int n0 = ni * 128;

    float acc[4][4][4];
#pragma unroll
    for (int i = 0; i < 4; i++)
#pragma unroll
        for (int j = 0; j < 4; j++)
#pragma unroll
            for (int k = 0; k < 4; k++) acc[i][j][k] = 0.f;

    auto issue = [&](int stg, int kb) {
        float* as = As + stg * 128 * 36;
        float* bs = Bs + stg * 128 * 36;
#pragma unroll
        for (int r = 0; r < 4; r++) {
            int f = tid + r * 256; int row = f >> 3, c4 = f & 7;
            cpa16(&as[row * 36 + c4 * 4],
                  A + (size_t)(m0 + row) * 1024 + kb + c4 * 4);
        }
#pragma unroll
        for (int r = 0; r < 4; r++) {
            int f = tid + r * 256; int row = f >> 3, c4 = f & 7;
            cpa16(&bs[row * 36 + c4 * 4],
                  BT + (size_t)(n0 + row) * 1024 + kb + c4 * 4);
        }
    };

    issue(0, 0);  cp_commit();
    issue(1, 32); cp_commit();
    issue(2, 64); cp_commit();

    for (int kbi = 0; kbi < 32; kbi++) {
        cp_wait<2>();                    // stage kbi landed
        __syncthreads();                 // all warps done with stage (kbi+3)&3
        if (kbi + 3 < 32) issue((kbi + 3) & 3, (kbi + 3) * 32);
        cp_commit();                     // uniform group count
        const uint32_t* as = (const uint32_t*)(As + (kbi & 3) * 128 * 36);
        const uint32_t* bs = (const uint32_t*)(Bs + (kbi & 3) * 128 * 36);
#pragma unroll
        for (int kk = 0; kk < 32; kk += 8) {
            uint32_t a[4][4], b[4][2];
#pragma unroll
            for (int mt = 0; mt < 4; mt++) {
                int r0 = wm * 64 + mt * 16 + g;
                a[mt][0] = as[r0 * 36 + kk + tg];
                a[mt][1] = as[(r0 + 8) * 36 + kk + tg];
                a[mt][2] = as[r0 * 36 + kk + 4 + tg];
                a[mt][3] = as[(r0 + 8) * 36 + kk + 4 + tg];
            }
#pragma unroll
            for (int nt = 0; nt < 4; nt++) {
                int nr = wn * 32 + nt * 8 + g;
                b[nt][0] = bs[nr * 36 + kk + tg];
                b[nt][1] = bs[nr * 36 + kk + 4 + tg];
            }
#pragma unroll
            for (int mt = 0; mt < 4; mt++)
#pragma unroll
                for (int nt = 0; nt < 4; nt++) mma_tf32(acc[mt][nt], a[mt], b[nt]);
        }
    }

    // epilogue
#pragma unroll
    for (int mt = 0; mt < 4; mt++) {
#pragma unroll
        for (int nt = 0; nt < 4; nt++) {
            int row = m0 + wm * 64 + mt * 16 + g;
            int col = n0 + wn * 32 + nt * 8 + 2 * tg;
#pragma unroll
            for (int h = 0; h < 2; h++) {
                int gr = row + h * 8;
                float b0, b1;
                float v0 = acc[mt][nt][h * 2 + 0];
                float v1 = acc[mt][nt][h * 2 + 1];
                if (mode == 0) { b0 = g_bg[col]; b1 = g_bg[col + 1]; }
                else           { b0 = bias_post[col]; b1 = bias_post[col + 1]; }
                float2 v = make_float2(v0 + b0, v1 + b1);
                if (mode == 0) {
                    *(float2*)(g_Gpre + (size_t)gr * 4096 + col) = v;
                } else {
                    size_t o = ((size_t)(gr & 63) * 512 + (gr >> 6)) * 1024 + col;
                    *(float2*)(Cpost + o) = v;
                }
            }
        }
    }
}

// ---------------- persistent recurrence (exact R11 winner) ------------------
// 128 CTAs x 512 thr, 512 steps. CTA owns gate columns [n0, n0+32).
// Split-K x2: warpgroup wg (= wid>>3) computes K[wg*512,(wg+1)*512).
// SMEM: Bf (fragment-packed W_h, 128KB) | Ast (3 stages x [2 wg][64][36])
//       | Gs (Gpre[t] tile 64x32). Partials combined in gate exchange.
static const int AST_HALF  = 64 * 36;                 // 2304 floats per wg-half
static const int AST_STAGE = 2 * AST_HALF;            // 4608 floats per stage
static const int REC_SMEM  = (32768 + 3 * AST_STAGE + 2048) * 4;  // 194560 B

__global__ void __launch_bounds__(512) k_rec() {
    extern __shared__ float smr[];
    float* Bf  = smr;                     // [128 k8][2 wn][32 lane][4] = 128KB
    float* Ast = smr + 32768;             // 3 stages [2][64][36]; aliased as gb
    float* Gs  = smr + 32768 + 3 * AST_STAGE;   // [64][32] Gpre tile

    const int tid = threadIdx.x, lane = tid & 31, wid = tid >> 5;
    const int wg = wid >> 3;              // warpgroup: K half
    const int wl = wid & 7;
    const int wm = wl & 3, wn = wl >> 2;
    const int g = lane >> 2, tg = lane & 3;
    const int n0 = blockIdx.x * 32;
    const int bid = blockIdx.x;

    // ---- build fragment-packed W_h slice in SMEM (once) ----
#pragma unroll 4
    for (int e = tid; e < 8192; e += 512) {
        int lane_e = e & 31, wn_e = (e >> 5) & 1, k8 = e >> 6;
        int ge = lane_e >> 2, tge = lane_e & 3;
        const float* w0 = g_WhT + (size_t)(n0 + wn_e * 16 + ge) * 1024 + k8 * 8 + tge;
        float4 v;
        v.x = w0[0];
        v.y = w0[4];
        v.z = w0[8 * 1024];
        v.w = w0[8 * 1024 + 4];
        *(float4*)(Bf + (size_t)e * 4) = v;
    }

    // ---- cell state in registers (1 item/thread) ----
    const int eb = tid >> 3, eu = tid & 7;           // elementwise (b, unit)
    float creg = g_c[(size_t)eb * 1024 + (n0 >> 2) + eu];

    // ---- barrier base: all flags equal at launch start (monotonic) ----
    __shared__ unsigned sh_base;
    if (tid == 0) sh_base = ldacq(&g_flags[bid * 32]);
    __syncthreads();
    const unsigned base = sh_base;

    // per-warp fragment base: Bf + (k8*2 + wn)*32 + lane  (float4 units)
    const float4* bfw = (const float4*)Bf + wn * 32 + lane;
    const int k8off = wg * 64;                        // wg's K half in k8 units

    for (int t = 0; t < 512; t++) {
        const float* hin  = (t == 0) ? g_h0 : g_Hall + (size_t)(t - 1) * 64 * 1024;
        float* hall       = g_Hall + (size_t)t * 64 * 1024;
        const float* gpre = g_Gpre + (size_t)t * 64 * 4096;

        // stage loads BOTH K halves: 1024 float4 per stage / 512 thr = 2 each
        auto issueA = [&](int stg, int kb) {
            float* as = Ast + stg * AST_STAGE;
#pragma unroll
            for (int r = 0; r < 2; r++) {
                int f = tid + r * 512;                // 0..1023
                int c4 = f & 7, row128 = f >> 3;
                int half = row128 >> 6, row = row128 & 63;
                cpa16(&as[half * AST_HALF + row * 36 + c4 * 4],
                      hin + (size_t)row * 1024 + kb + half * 512 + c4 * 4);
            }
        };

        float acc[2][4];
#pragma unroll
        for (int i = 0; i < 2; i++)
#pragma unroll
            for (int k = 0; k < 4; k++) acc[i][k] = 0.f;

        // prefill: Gs (1 float4/thread) + stage0 in one group, then stage1
        {
            int row = tid >> 3, c4 = tid & 7;
            cpa16(&Gs[row * 32 + c4 * 4],
                  gpre + (size_t)row * 4096 + n0 + c4 * 4);
        }
        issueA(0, 0);  cp_commit();
        issueA(1, 32); cp_commit();

        for (int kbi = 0; kbi < 16; kbi++) {
            cp_wait<1>();
            __syncthreads();
            const uint32_t* as = (const uint32_t*)(Ast + (kbi % 3) * AST_STAGE
                                                   + wg * AST_HALF);
#pragma unroll
            for (int kk = 0; kk < 32; kk += 8) {
                int k8 = k8off + kbi * 4 + (kk >> 3);
                uint32_t a[4];
                int r0 = wm * 16 + g;
                a[0] = as[r0 * 36 + kk + tg];
                a[1] = as[(r0 + 8) * 36 + kk + tg];
                a[2] = as[r0 * 36 + kk + 4 + tg];
                a[3] = as[(r0 + 8) * 36 + kk + 4 + tg];
                float4 bv = bfw[k8 * 64];
                uint32_t b0[2] = { __float_as_uint(bv.x), __float_as_uint(bv.y) };
                uint32_t b1[2] = { __float_as_uint(bv.z), __float_as_uint(bv.w) };
                mma_tf32(acc[0], a, b0);
                mma_tf32(acc[1], a, b1);
            }
            if (kbi + 2 < 16) issueA((kbi + 2) % 3, (kbi + 2) * 32);
            cp_commit();
        }

        // ---- gate exchange: each wg writes its partial, then combine ----
        cp_wait<0>();
        __syncthreads();
        float* gb = Ast;                  // [2 wg][64][36], cols 0..31 used
        float* gbw = gb + wg * AST_HALF;
#pragma unroll
        for (int nt = 0; nt < 2; nt++) {
            int row = wm * 16 + g, col = wn * 16 + nt * 8 + 2 * tg;
            gbw[row * 36 + col]           = acc[nt][0];
            gbw[row * 36 + col + 1]       = acc[nt][1];
            gbw[(row + 8) * 36 + col]     = acc[nt][2];
            gbw[(row + 8) * 36 + col + 1] = acc[nt][3];
        }
        __syncthreads();

        // ---- fused LSTM elementwise: 512 items, 1 per thread ----
        {
            int cl = 4 * eu;
            int o = eb * 36 + cl;
            float gf = Gs[eb * 32 + cl]     + gb[o]     + gb[AST_HALF + o];
            float gi = Gs[eb * 32 + cl + 1] + gb[o + 1] + gb[AST_HALF + o + 1];
            float gc = Gs[eb * 32 + cl + 2] + gb[o + 2] + gb[AST_HALF + o + 2];
            float go = Gs[eb * 32 + cl + 3] + gb[o + 3] + gb[AST_HALF + o + 3];
            float f  = sigm(gf);
            float i  = sigm(gi);
            float ch = tanh_f(gc);
            float oo = sigm(go);
            float cn = f * creg + i * ch;
            creg = cn;
            float hr = tf32r(oo * tanh_f(cn));
            hall[(size_t)eb * 1024 + (n0 >> 2) + eu] = hr;
        }

        // ---- flat all-poll grid barrier (monotonic flags) ----
        const unsigned target = base + (unsigned)t + 1u;
        __syncthreads();                            // all h writes done
        if (tid == 0) strel(&g_flags[bid * 32], target);
        if (tid < 128) {
            while ((int)(ldacq(&g_flags[tid * 32]) - target) < 0) __nanosleep(32);
        }
        __syncthreads();                            // all threads see new h
    }
}

// ---------------- launch -----------------------------------------------------
extern "C" void kernel_launch(void* const* d_in, const int* in_sizes, int n_in,
                              void* d_out, int out_size) {
    const float* x    = (const float*)d_in[0];
    const float* h0   = (const float*)d_in[1];
    const float* c0   = (const float*)d_in[2];
    const float* W_f  = (const float*)d_in[3];
    const float* b_f  = (const float*)d_in[4];
    const float* W_i  = (const float*)d_in[5];
    const float* b_i  = (const float*)d_in[6];
    const float* W_c  = (const float*)d_in[7];
    const float* b_c  = (const float*)d_in[8];
    const float* W_o  = (const float*)d_in[9];
    const float* b_o  = (const float*)d_in[10];
    const float* W_out = (const float*)d_in[11];
    const float* b_out = (const float*)d_in[12];
    float* out = (float*)d_out;

    cudaFuncSetAttribute(k_gemm, cudaFuncAttributeMaxDynamicSharedMemorySize, GEMM_SMEM);
    cudaFuncSetAttribute(k_rec,  cudaFuncAttributeMaxDynamicSharedMemorySize, REC_SMEM);

    // 6 launches; slot 4 = pre-GEMM (this round's variable gets profiled).
    k_prepA<<<33024, 256>>>(x, b_f, b_i, b_c, b_o, h0, c0);
    k_prep_w<<<8192, dim3(32, 8)>>>(W_f, W_i, W_c, W_o);
    k_prep_wout<<<1024, dim3(32, 8)>>>(W_out);

    // pre-GEMM: G_pre (M=32768, N=4096), 8192 CTAs supertiled
    k_gemm<<<8192, 256, GEMM_SMEM>>>(nullptr, nullptr, 0);

    // persistent recurrence: all 512 steps in one kernel (R11 config)
    k_rec<<<128, 512, REC_SMEM>>>();

    // post-GEMM: out (M=32768, N=1024), 2048 CTAs supertiled
    k_gemm<<<2048, 256, GEMM_SMEM>>>(out, b_out, 1);
}

// round 15
// speedup vs baseline: 1.0723x; 1.0479x over previous
#include <cuda_runtime.h>
#include <cstdint>
#include <math.h>

// ---------------------------------------------------------------------------
// LSTM  B=64 S=512 D=1024 H=1024 F=1024
//  1) G_pre = Xt @ WxT^T + b_g      (tf32 GEMM, M=32768 N=4096 K=1024)
//  2) ONE persistent kernel, 128 CTAs x 512 thr, 512 steps (R11 config):
//       gates = G_pre[t] + h@WhT^T ; fused LSTM elementwise
//     Split-K x2 across warpgroups; shared 3-stage cp.async pipeline;
//     W_h fragment-packed in SMEM; c in registers; flat all-poll barrier.
//  3) out = Hall @ WoT^T + b_out    (tf32 GEMM, M=32768 N=1024 K=1024)
// Big GEMMs: 3-stage ring (110KB smem -> 2 CTAs/SM), issue-before-compute
// (2 groups in flight during compute). R13's 4-stage ring is reverted: its
// 147KB smem halved GEMM occupancy (1 CTA/SM) and cost ~500us.
// ---------------------------------------------------------------------------

#define DEVINL __device__ __forceinline__

// ---------------- static device scratch (no runtime allocation) ------------
__device__ float g_Xt  [(size_t)32768 * 1024];   // x as (t,b) rows, tf32-rounded
__device__ float g_Gpre[(size_t)32768 * 4096];   // x-part of gates (+bias)
__device__ float g_Hall[(size_t)32768 * 1024];   // all h_t, tf32-rounded
__device__ float g_WxT [(size_t)4096 * 1024];    // [n][k] interleaved, x rows
__device__ float g_WhT [(size_t)4096 * 1024];    // [n][k] interleaved, h rows
__device__ float g_WoT [(size_t)1024 * 1024];    // W_out^T [f][h]
__device__ float g_bg  [4096];                   // gate bias, interleaved
__device__ float g_h0  [64 * 1024];              // initial h (tf32-rounded)
__device__ float g_c   [64 * 1024];              // cell state (init only)

// grid-barrier state: monotonic counters (never reset; base read per launch)
__device__ unsigned g_flags[128 * 32];           // flag i at [i*32] (own 128B line)

// ---------------- helpers ---------------------------------------------------
DEVINL uint32_t f2tf32(float x) {
    uint32_t r; asm("cvt.rna.tf32.f32 %0, %1;" : "=r"(r) : "f"(x)); return r;
}
DEVINL float tf32r(float x) { return __uint_as_float(f2tf32(x)); }

DEVINL void cpa16(void* dst, const void* src) {
    uint32_t d = (uint32_t)__cvta_generic_to_shared(dst);
    asm volatile("cp.async.cg.shared.global [%0], [%1], 16;\n" :: "r"(d), "l"(src));
}
DEVINL void cp_commit() { asm volatile("cp.async.commit_group;\n"); }
template <int N> DEVINL void cp_wait() { asm volatile("cp.async.wait_group %0;\n" :: "n"(N)); }

DEVINL void mma_tf32(float* c, const uint32_t* a, const uint32_t* b) {
    asm volatile(
        "mma.sync.aligned.m16n8k8.row.col.f32.tf32.tf32.f32 "
        "{%0,%1,%2,%3},{%4,%5,%6,%7},{%8,%9},{%0,%1,%2,%3};\n"
        : "+f"(c[0]), "+f"(c[1]), "+f"(c[2]), "+f"(c[3])
        : "r"(a[0]), "r"(a[1]), "r"(a[2]), "r"(a[3]), "r"(b[0]), "r"(b[1]));
}
DEVINL float sigm(float x)   { return 1.f / (1.f + __expf(-x)); }
DEVINL float tanh_f(float x) { return 2.f / (1.f + __expf(-2.f * x)) - 1.f; }

DEVINL unsigned ldacq(const unsigned* p) {
    unsigned v; asm volatile("ld.acquire.gpu.global.u32 %0, [%1];" : "=r"(v) : "l"(p)); return v;
}
DEVINL void strel(unsigned* p, unsigned v) {
    asm volatile("st.release.gpu.global.u32 [%0], %1;" :: "l"(p), "r"(v));
}

// ---------------- prepA: x transform + bias/state init ----------------------
__global__ void __launch_bounds__(256) k_prepA(
        const float* __restrict__ x,
        const float* __restrict__ bf, const float* __restrict__ bi,
        const float* __restrict__ bc, const float* __restrict__ bo,
        const float* __restrict__ h0, const float* __restrict__ c0) {
    if (blockIdx.x < 32768) {
        size_t p = (size_t)blockIdx.x * 256 + threadIdx.x;
        int d4 = (int)(p & 255);
        size_t m = p >> 8;
        int b = (int)(m & 63), t = (int)(m >> 6);
        float4 v = *(const float4*)(x + ((size_t)b * 512 + t) * 1024 + (size_t)d4 * 4);
        v.x = tf32r(v.x); v.y = tf32r(v.y); v.z = tf32r(v.z); v.w = tf32r(v.w);
        *(float4*)(g_Xt + m * 1024 + (size_t)d4 * 4) = v;
    } else {
        int i = (blockIdx.x - 32768) * 256 + threadIdx.x;   // 0..65535
        if (i < 4096) {
            int u = i >> 2, gt = i & 3;
            const float* b = (gt == 0) ? bf : (gt == 1) ? bi : (gt == 2) ? bc : bo;
            g_bg[i] = b[u];
        }
        g_h0[i] = tf32r(h0[i]);
        g_c[i]  = c0[i];
    }
}

// ---------------- prep_w: gate weight transposes -----------------------------
__global__ void k_prep_w(const float* __restrict__ Wf, const float* __restrict__ Wi,
                         const float* __restrict__ Wc, const float* __restrict__ Wo) {
    __shared__ float tile[32][33];
    int tx = threadIdx.x, ty = threadIdx.y;
    int bid = blockIdx.x;
    int s    = bid >> 12;         // 0 = x rows, 1 = h rows
    int gate = (bid >> 10) & 3;
    int kt   = (bid >> 5) & 31;
    int ut   = bid & 31;
    const float* W = (gate == 0) ? Wf : (gate == 1) ? Wi : (gate == 2) ? Wc : Wo;
#pragma unroll
    for (int r = 0; r < 4; r++) {
        int k = kt * 32 + ty + r * 8;
        tile[ty + r * 8][tx] = W[(size_t)(s * 1024 + k) * 1024 + ut * 32 + tx];
    }
    __syncthreads();
    float* WT = s ? g_WhT : g_WxT;
#pragma unroll
    for (int r = 0; r < 4; r++) {
        int ul = ty + r * 8;
        int n = 4 * (ut * 32 + ul) + gate;
        WT[(size_t)n * 1024 + kt * 32 + tx] = tf32r(tile[tx][ul]);
    }
}

// ---------------- prep_wout: W_out transpose ----------------------------------
__global__ void k_prep_wout(const float* __restrict__ Wout) {
    __shared__ float tile[32][33];
    int tx = threadIdx.x, ty = threadIdx.y;
    int ft = blockIdx.x & 31, ht = blockIdx.x >> 5;
#pragma unroll
    for (int r = 0; r < 4; r++) {
        int h = ht * 32 + ty + r * 8;
        tile[ty + r * 8][tx] = Wout[(size_t)h * 1024 + ft * 32 + tx];
    }
    __syncthreads();
#pragma unroll
    for (int r = 0; r < 4; r++) {
        int fl = ty + r * 8;
        int f = ft * 32 + fl;
        g_WoT[(size_t)f * 1024 + ht * 32 + tx] = tf32r(tile[tx][fl]);
    }
}

// ---------------- big tf32 GEMM: BM=128 BN=128 BK=32, 256 thr, 3-stage -----
// 110592 B smem -> 2 CTAs/SM. Issue-before-compute: 2 groups in flight.
static const int GEMM_SMEM = 3 * 2 * 128 * 36 * 4;   // 110592 B

__global__ void __launch_bounds__(256) k_gemm(float* __restrict__ Cpost,
                                              const float* __restrict__ bias_post,
                                              int mode) {
    extern __shared__ float sm[];
    const float* A  = mode ? g_Hall : g_Xt;
    const float* BT = mode ? g_WoT  : g_WxT;
    float* As = sm;                    // [3][128][36]
    float* Bs = sm + 3 * 128 * 36;     // [3][128][36]

    const int tid = threadIdx.x, lane = tid & 31, wid = tid >> 5;
    const int wm = wid & 1, wn = wid >> 1;          // 2 x 4 warps
    const int g = lane >> 2, tg = lane & 3;

    int mi, ni;
    if (mode == 0) {                     // 32 n-blocks
        int sup = blockIdx.x >> 8, rem = blockIdx.x & 255;
        mi = sup * 8 + (rem & 7); ni = rem >> 3;
    } else {                             // 8 n-blocks
        int sup = blockIdx.x >> 6, rem = blockIdx.x & 63;
        mi = sup * 8 + (rem & 7); ni = rem >> 3;
    }
    const int m0 = mi * 128;
    const int n0 = ni * 128;

    float acc[4][4][4];
#pragma unroll
    for (int i = 0; i < 4; i++)
#pragma unroll
        for (int j = 0; j < 4; j++)
#pragma unroll
            for (int k = 0; k < 4; k++) acc[i][j][k] = 0.f;

    auto issue = [&](int stg, int kb) {
        float* as = As + stg * 128 * 36;
        float* bs = Bs + stg * 128 * 36;
#pragma unroll
        for (int r = 0; r < 4; r++) {
            int f = tid + r * 256; int row = f >> 3, c4 = f & 7;
            cpa16(&as[row * 36 + c4 * 4],
                  A + (size_t)(m0 + row) * 1024 + kb + c4 * 4);
        }
#pragma unroll
        for (int r = 0; r < 4; r++) {
            int f = tid + r * 256; int row = f >> 3, c4 = f & 7;
            cpa16(&bs[row * 36 + c4 * 4],
                  BT + (size_t)(n0 + row) * 1024 + kb + c4 * 4);
        }
    };

    issue(0, 0);  cp_commit();
    issue(1, 32); cp_commit();

    for (int kbi = 0; kbi < 32; kbi++) {
        cp_wait<1>();                    // stage kbi landed
        __syncthreads();                 // all warps done with stage (kbi+2)%3
        if (kbi + 2 < 32) issue((kbi + 2) % 3, (kbi + 2) * 32);
        cp_commit();                     // uniform group count
        const uint32_t* as = (const uint32_t*)(As + (kbi % 3) * 128 * 36);
        const uint32_t* bs = (const uint32_t*)(Bs + (kbi % 3) * 128 * 36);
#pragma unroll
        for (int kk = 0; kk < 32; kk += 8) {
            uint32_t a[4][4], b[4][2];
#pragma unroll
            for (int mt = 0; mt < 4; mt++) {
                int r0 = wm * 64 + mt * 16 + g;
                a[mt][0] = as[r0 * 36 + kk + tg];
                a[mt][1] = as[(r0 + 8) * 36 + kk + tg];
                a[mt][2] = as[r0 * 36 + kk + 4 + tg];
                a[mt][3] = as[(r0 + 8) * 36 + kk + 4 + tg];
            }
#pragma unroll
            for (int nt = 0; nt < 4; nt++) {
                int nr = wn * 32 + nt * 8 + g;
                b[nt][0] = bs[nr * 36 + kk + tg];
                b[nt][1] = bs[nr * 36 + kk + 4 + tg];
            }
#pragma unroll
            for (int mt = 0; mt < 4; mt++)
#pragma unroll
                for (int nt = 0; nt < 4; nt++) mma_tf32(acc[mt][nt], a[mt], b[nt]);
        }
    }

    // epilogue
#pragma unroll
    for (int mt = 0; mt < 4; mt++) {
#pragma unroll
        for (int nt = 0; nt < 4; nt++) {
            int row = m0 + wm * 64 + mt * 16 + g;
            int col = n0 + wn * 32 + nt * 8 + 2 * tg;
#pragma unroll
            for (int h = 0; h < 2; h++) {
                int gr = row + h * 8;
                float b0, b1;
                float v0 = acc[mt][nt][h * 2 + 0];
                float v1 = acc[mt][nt][h * 2 + 1];
                if (mode == 0) { b0 = g_bg[col]; b1 = g_bg[col + 1]; }
                else           { b0 = bias_post[col]; b1 = bias_post[col + 1]; }
                float2 v = make_float2(v0 + b0, v1 + b1);
                if (mode == 0) {
                    *(float2*)(g_Gpre + (size_t)gr * 4096 + col) = v;
                } else {
                    size_t o = ((size_t)(gr & 63) * 512 + (gr >> 6)) * 1024 + col;
                    *(float2*)(Cpost + o) = v;
                }
            }
        }
    }
}

// ---------------- persistent recurrence (exact R11 winner) ------------------
// 128 CTAs x 512 thr, 512 steps. CTA owns gate columns [n0, n0+32).
// Split-K x2: warpgroup wg (= wid>>3) computes K[wg*512,(wg+1)*512).
// SMEM: Bf (fragment-packed W_h, 128KB) | Ast (3 stages x [2 wg][64][36])
//       | Gs (Gpre[t] tile 64x32). Partials combined in gate exchange.
static const int AST_HALF  = 64 * 36;                 // 2304 floats per wg-half
static const int AST_STAGE = 2 * AST_HALF;            // 4608 floats per stage
static const int REC_SMEM  = (32768 + 3 * AST_STAGE + 2048) * 4;  // 194560 B

__global__ void __launch_bounds__(512) k_rec() {
    extern __shared__ float smr[];
    float* Bf  = smr;                     // [128 k8][2 wn][32 lane][4] = 128KB
    float* Ast = smr + 32768;             // 3 stages [2][64][36]; aliased as gb
    float* Gs  = smr + 32768 + 3 * AST_STAGE;   // [64][32] Gpre tile

    const int tid = threadIdx.x, lane = tid & 31, wid = tid >> 5;
    const int wg = wid >> 3;              // warpgroup: K half
    const int wl = wid & 7;
    const int wm = wl & 3, wn = wl >> 2;
    const int g = lane >> 2, tg = lane & 3;
    const int n0 = blockIdx.x * 32;
    const int bid = blockIdx.x;

    // ---- build fragment-packed W_h slice in SMEM (once) ----
#pragma unroll 4
    for (int e = tid; e < 8192; e += 512) {
        int lane_e = e & 31, wn_e = (e >> 5) & 1, k8 = e >> 6;
        int ge = lane_e >> 2, tge = lane_e & 3;
        const float* w0 = g_WhT + (size_t)(n0 + wn_e * 16 + ge) * 1024 + k8 * 8 + tge;
        float4 v;
        v.x = w0[0];
        v.y = w0[4];
        v.z = w0[8 * 1024];
        v.w = w0[8 * 1024 + 4];
        *(float4*)(Bf + (size_t)e * 4) = v;
    }

    // ---- cell state in registers (1 item/thread) ----
    const int eb = tid >> 3, eu = tid & 7;           // elementwise (b, unit)
    float creg = g_c[(size_t)eb * 1024 + (n0 >> 2) + eu];

    // ---- barrier base: all flags equal at launch start (monotonic) ----
    __shared__ unsigned sh_base;
    if (tid == 0) sh_base = ldacq(&g_flags[bid * 32]);
    __syncthreads();
    const unsigned base = sh_base;

    // per-warp fragment base: Bf + (k8*2 + wn)*32 + lane  (float4 units)
    const float4* bfw = (const float4*)Bf + wn * 32 + lane;
    const int k8off = wg * 64;                        // wg's K half in k8 units

    for (int t = 0; t < 512; t++) {
        const float* hin  = (t == 0) ? g_h0 : g_Hall + (size_t)(t - 1) * 64 * 1024;
        float* hall       = g_Hall + (size_t)t * 64 * 1024;
        const float* gpre = g_Gpre + (size_t)t * 64 * 4096;

        // stage loads BOTH K halves: 1024 float4 per stage / 512 thr = 2 each
        auto issueA = [&](int stg, int kb) {
            float* as = Ast + stg * AST_STAGE;
#pragma unroll
            for (int r = 0; r < 2; r++) {
                int f = tid + r * 512;                // 0..1023
                int c4 = f & 7, row128 = f >> 3;
                int half = row128 >> 6, row = row128 & 63;
                cpa16(&as[half * AST_HALF + row * 36 + c4 * 4],
                      hin + (size_t)row * 1024 + kb + half * 512 + c4 * 4);
            }
        };

        float acc[2][4];
#pragma unroll
        for (int i = 0; i < 2; i++)
#pragma unroll
            for (int k = 0; k < 4; k++) acc[i][k] = 0.f;

        // prefill: Gs (1 float4/thread) + stage0 in one group, then stage1
        {
            int row = tid >> 3, c4 = tid & 7;
            cpa16(&Gs[row * 32 + c4 * 4],
                  gpre + (size_t)row * 4096 + n0 + c4 * 4);
        }
        issueA(0, 0);  cp_commit();
        issueA(1, 32); cp_commit();

        for (int kbi = 0; kbi < 16; kbi++) {
            cp_wait<1>();
            __syncthreads();
            const uint32_t* as = (const uint32_t*)(Ast + (kbi % 3) * AST_STAGE
                                                   + wg * AST_HALF);
#pragma unroll
            for (int kk = 0; kk < 32; kk += 8) {
                int k8 = k8off + kbi * 4 + (kk >> 3);
                uint32_t a[4];
                int r0 = wm * 16 + g;
                a[0] = as[r0 * 36 + kk + tg];
                a[1] = as[(r0 + 8) * 36 + kk + tg];
                a[2] = as[r0 * 36 + kk + 4 + tg];
                a[3] = as[(r0 + 8) * 36 + kk + 4 + tg];
                float4 bv = bfw[k8 * 64];
                uint32_t b0[2] = { __float_as_uint(bv.x), __float_as_uint(bv.y) };
                uint32_t b1[2] = { __float_as_uint(bv.z), __float_as_uint(bv.w) };
                mma_tf32(acc[0], a, b0);
                mma_tf32(acc[1], a, b1);
            }
            if (kbi + 2 < 16) issueA((kbi + 2) % 3, (kbi + 2) * 32);
            cp_commit();
        }

        // ---- gate exchange: each wg writes its partial, then combine ----
        cp_wait<0>();
        __syncthreads();
        float* gb = Ast;                  // [2 wg][64][36], cols 0..31 used
        float* gbw = gb + wg * AST_HALF;
#pragma unroll
        for (int nt = 0; nt < 2; nt++) {
            int row = wm * 16 + g, col = wn * 16 + nt * 8 + 2 * tg;
            gbw[row * 36 + col]           = acc[nt][0];
            gbw[row * 36 + col + 1]       = acc[nt][1];
            gbw[(row + 8) * 36 + col]     = acc[nt][2];
            gbw[(row + 8) * 36 + col + 1] = acc[nt][3];
        }
        __syncthreads();

        // ---- fused LSTM elementwise: 512 items, 1 per thread ----
        {
            int cl = 4 * eu;
            int o = eb * 36 + cl;
            float gf = Gs[eb * 32 + cl]     + gb[o]     + gb[AST_HALF + o];
            float gi = Gs[eb * 32 + cl + 1] + gb[o + 1] + gb[AST_HALF + o + 1];
            float gc = Gs[eb * 32 + cl + 2] + gb[o + 2] + gb[AST_HALF + o + 2];
            float go = Gs[eb * 32 + cl + 3] + gb[o + 3] + gb[AST_HALF + o + 3];
            float f  = sigm(gf);
            float i  = sigm(gi);
            float ch = tanh_f(gc);
            float oo = sigm(go);
            float cn = f * creg + i * ch;
            creg = cn;
            float hr = tf32r(oo * tanh_f(cn));
            hall[(size_t)eb * 1024 + (n0 >> 2) + eu] = hr;
        }

        // ---- flat all-poll grid barrier (monotonic flags) ----
        const unsigned target = base + (unsigned)t + 1u;
        __syncthreads();                            // all h writes done
        if (tid == 0) strel(&g_flags[bid * 32], target);
        if (tid < 128) {
            while ((int)(ldacq(&g_flags[tid * 32]) - target) < 0) __nanosleep(32);
        }
        __syncthreads();                            // all threads see new h
    }
}

// ---------------- launch -----------------------------------------------------
extern "C" void kernel_launch(void* const* d_in, const int* in_sizes, int n_in,
                              void* d_out, int out_size) {
    const float* x    = (const float*)d_in[0];
    const float* h0   = (const float*)d_in[1];
    const float* c0   = (const float*)d_in[2];
    const float* W_f  = (const float*)d_in[3];
    const float* b_f  = (const float*)d_in[4];
    const float* W_i  = (const float*)d_in[5];
    const float* b_i  = (const float*)d_in[6];
    const float* W_c  = (const float*)d_in[7];
    const float* b_c  = (const float*)d_in[8];
    const float* W_o  = (const float*)d_in[9];
    const float* b_o  = (const float*)d_in[10];
    const float* W_out = (const float*)d_in[11];
    const float* b_out = (const float*)d_in[12];
    float* out = (float*)d_out;

    cudaFuncSetAttribute(k_gemm, cudaFuncAttributeMaxDynamicSharedMemorySize, GEMM_SMEM);
    cudaFuncSetAttribute(k_rec,  cudaFuncAttributeMaxDynamicSharedMemorySize, REC_SMEM);

    // 6 launches; slot 4 = pre-GEMM (verify occ/tensor recovery).
    k_prepA<<<33024, 256>>>(x, b_f, b_i, b_c, b_o, h0, c0);
    k_prep_w<<<8192, dim3(32, 8)>>>(W_f, W_i, W_c, W_o);
    k_prep_wout<<<1024, dim3(32, 8)>>>(W_out);

    // pre-GEMM: G_pre (M=32768, N=4096), 8192 CTAs supertiled
    k_gemm<<<8192, 256, GEMM_SMEM>>>(nullptr, nullptr, 0);

    // persistent recurrence: all 512 steps in one kernel (R11 config)
    k_rec<<<128, 512, REC_SMEM>>>();

    // post-GEMM: out (M=32768, N=1024), 2048 CTAs supertiled
    k_gemm<<<2048, 256, GEMM_SMEM>>>(out, b_out, 1);
}

// round 16
// speedup vs baseline: 1.1018x; 1.0275x over previous
#include <cuda_runtime.h>
#include <cstdint>
#include <math.h>

// ---------------------------------------------------------------------------
// LSTM  B=64 S=512 D=1024 H=1024 F=1024
//  1) G_pre = Xt @ WxT^T + b_g      (tf32 GEMM, M=32768 N=4096 K=1024)
//  2) ONE persistent kernel, 128 CTAs x 512 thr, 512 steps:
//       gates = G_pre[t] + h@WhT^T ; fused LSTM elementwise
//     Split-K x4, warp tile 16x32 (4 mma share one A fragment -> 25% less
//     SMEM-crossbar traffic/mma). BK=16, 3-stage cp.async ring,
//     compute-then-issue, plain __syncthreads (all R11-proven params).
//     W_h fragment-packed in SMEM; c in registers; flat all-poll barrier.
//  3) out = Hall @ WoT^T + b_out    (tf32 GEMM, M=32768 N=1024 K=1024)
// Big GEMMs: exact R7/R11 winner (3-stage, compute-then-issue, 2 CTAs/SM).
// Gate columns interleaved: n = 4*unit + gate.
// ---------------------------------------------------------------------------

#define DEVINL __device__ __forceinline__

// ---------------- static device scratch (no runtime allocation) ------------
__device__ float g_Xt  [(size_t)32768 * 1024];   // x as (t,b) rows, tf32-rounded
__device__ float g_Gpre[(size_t)32768 * 4096];   // x-part of gates (+bias)
__device__ float g_Hall[(size_t)32768 * 1024];   // all h_t, tf32-rounded
__device__ float g_WxT [(size_t)4096 * 1024];    // [n][k] interleaved, x rows
__device__ float g_WhT [(size_t)4096 * 1024];    // [n][k] interleaved, h rows
__device__ float g_WoT [(size_t)1024 * 1024];    // W_out^T [f][h]
__device__ float g_bg  [4096];                   // gate bias, interleaved
__device__ float g_h0  [64 * 1024];              // initial h (tf32-rounded)
__device__ float g_c   [64 * 1024];              // cell state (init only)

// grid-barrier state: monotonic counters (never reset; base read per launch)
__device__ unsigned g_flags[128 * 32];           // flag i at [i*32] (own 128B line)

// ---------------- helpers ---------------------------------------------------
DEVINL uint32_t f2tf32(float x) {
    uint32_t r; asm("cvt.rna.tf32.f32 %0, %1;" : "=r"(r) : "f"(x)); return r;
}
DEVINL float tf32r(float x) { return __uint_as_float(f2tf32(x)); }

DEVINL void cpa16(void* dst, const void* src) {
    uint32_t d = (uint32_t)__cvta_generic_to_shared(dst);
    asm volatile("cp.async.cg.shared.global [%0], [%1], 16;\n" :: "r"(d), "l"(src));
}
DEVINL void cp_commit() { asm volatile("cp.async.commit_group;\n"); }
template <int N> DEVINL void cp_wait() { asm volatile("cp.async.wait_group %0;\n" :: "n"(N)); }

DEVINL void mma_tf32(float* c, const uint32_t* a, const uint32_t* b) {
    asm volatile(
        "mma.sync.aligned.m16n8k8.row.col.f32.tf32.tf32.f32 "
        "{%0,%1,%2,%3},{%4,%5,%6,%7},{%8,%9},{%0,%1,%2,%3};\n"
        : "+f"(c[0]), "+f"(c[1]), "+f"(c[2]), "+f"(c[3])
        : "r"(a[0]), "r"(a[1]), "r"(a[2]), "r"(a[3]), "r"(b[0]), "r"(b[1]));
}
DEVINL float sigm(float x)   { return 1.f / (1.f + __expf(-x)); }
DEVINL float tanh_f(float x) { return 2.f / (1.f + __expf(-2.f * x)) - 1.f; }

DEVINL unsigned ldacq(const unsigned* p) {
    unsigned v; asm volatile("ld.acquire.gpu.global.u32 %0, [%1];" : "=r"(v) : "l"(p)); return v;
}
DEVINL void strel(unsigned* p, unsigned v) {
    asm volatile("st.release.gpu.global.u32 [%0], %1;" :: "l"(p), "r"(v));
}

// ---------------- prepA: x transform + bias/state init ----------------------
__global__ void __launch_bounds__(256) k_prepA(
        const float* __restrict__ x,
        const float* __restrict__ bf, const float* __restrict__ bi,
        const float* __restrict__ bc, const float* __restrict__ bo,
        const float* __restrict__ h0, const float* __restrict__ c0) {
    if (blockIdx.x < 32768) {
        size_t p = (size_t)blockIdx.x * 256 + threadIdx.x;
        int d4 = (int)(p & 255);
        size_t m = p >> 8;
        int b = (int)(m & 63), t = (int)(m >> 6);
        float4 v = *(const float4*)(x + ((size_t)b * 512 + t) * 1024 + (size_t)d4 * 4);
        v.x = tf32r(v.x); v.y = tf32r(v.y); v.z = tf32r(v.z); v.w = tf32r(v.w);
        *(float4*)(g_Xt + m * 1024 + (size_t)d4 * 4) = v;
    } else {
        int i = (blockIdx.x - 32768) * 256 + threadIdx.x;   // 0..65535
        if (i < 4096) {
            int u = i >> 2, gt = i & 3;
            const float* b = (gt == 0) ? bf : (gt == 1) ? bi : (gt == 2) ? bc : bo;
            g_bg[i] = b[u];
        }
        g_h0[i] = tf32r(h0[i]);
        g_c[i]  = c0[i];
    }
}

// ---------------- prepB: weight transposes ----------------------------------
__global__ void k_prepB(const float* __restrict__ Wf, const float* __restrict__ Wi,
                        const float* __restrict__ Wc, const float* __restrict__ Wo,
                        const float* __restrict__ Wout) {
    __shared__ float tile[32][33];
    int tx = threadIdx.x, ty = threadIdx.y;
    if (blockIdx.x < 8192) {
        int bid = blockIdx.x;
        int s    = bid >> 12;         // 0 = x rows, 1 = h rows
        int gate = (bid >> 10) & 3;
        int kt   = (bid >> 5) & 31;
        int ut   = bid & 31;
        const float* W = (gate == 0) ? Wf : (gate == 1) ? Wi : (gate == 2) ? Wc : Wo;
#pragma unroll
        for (int r = 0; r < 4; r++) {
            int k = kt * 32 + ty + r * 8;
            tile[ty + r * 8][tx] = W[(size_t)(s * 1024 + k) * 1024 + ut * 32 + tx];
        }
        __syncthreads();
        float* WT = s ? g_WhT : g_WxT;
#pragma unroll
        for (int r = 0; r < 4; r++) {
            int ul = ty + r * 8;
            int n = 4 * (ut * 32 + ul) + gate;
            WT[(size_t)n * 1024 + kt * 32 + tx] = tf32r(tile[tx][ul]);
        }
    } else {
        int bid = blockIdx.x - 8192;
        int ft = bid & 31, ht = bid >> 5;
#pragma unroll
        for (int r = 0; r < 4; r++) {
            int h = ht * 32 + ty + r * 8;
            tile[ty + r * 8][tx] = Wout[(size_t)h * 1024 + ft * 32 + tx];
        }
        __syncthreads();
#pragma unroll
        for (int r = 0; r < 4; r++) {
            int fl = ty + r * 8;
            int f = ft * 32 + fl;
            g_WoT[(size_t)f * 1024 + ht * 32 + tx] = tf32r(tile[tx][fl]);
        }
    }
}

// ---------------- big tf32 GEMM (exact R7/R11 winner) ------------------------
// BM=128 BN=128 BK=32, 256 thr, 3-stage, compute-then-issue, 2 CTAs/SM.
static const int GEMM_SMEM = 3 * 2 * 128 * 36 * 4;   // 110592 B

__global__ void __launch_bounds__(256) k_gemm(float* __restrict__ Cpost,
                                              const float* __restrict__ bias_post,
                                              int mode) {
    extern __shared__ float sm[];
    const float* A  = mode ? g_Hall : g_Xt;
    const float* BT = mode ? g_WoT  : g_WxT;
    float* As = sm;                    // [3][128][36]
    float* Bs = sm + 3 * 128 * 36;     // [3][128][36]

    const int tid = threadIdx.x, lane = tid & 31, wid = tid >> 5;
    const int wm = wid & 1, wn = wid >> 1;          // 2 x 4 warps
    const int g = lane >> 2, tg = lane & 3;

    int mi, ni;
    if (mode == 0) {                     // 32 n-blocks
        int sup = blockIdx.x >> 8, rem = blockIdx.x & 255;
        mi = sup * 8 + (rem & 7); ni = rem >> 3;
    } else {                             // 8 n-blocks
        int sup = blockIdx.x >> 6, rem = blockIdx.x & 63;
        mi = sup * 8 + (rem & 7); ni = rem >> 3;
    }
    const int m0 = mi * 128;
    const int n0 = ni * 128;

    float acc[4][4][4];
#pragma unroll
    for (int i = 0; i < 4; i++)
#pragma unroll
        for (int j = 0; j < 4; j++)
#pragma unroll
            for (int k = 0; k < 4; k++) acc[i][j][k] = 0.f;

    auto issue = [&](int stg, int kb) {
        float* as = As + stg * 128 * 36;
        float* bs = Bs + stg * 128 * 36;
#pragma unroll
        for (int r = 0; r < 4; r++) {
            int f = tid + r * 256; int row = f >> 3, c4 = f & 7;
            cpa16(&as[row * 36 + c4 * 4],
                  A + (size_t)(m0 + row) * 1024 + kb + c4 * 4);
        }
#pragma unroll
        for (int r = 0; r < 4; r++) {
            int f = tid + r * 256; int row = f >> 3, c4 = f & 7;
            cpa16(&bs[row * 36 + c4 * 4],
                  BT + (size_t)(n0 + row) * 1024 + kb + c4 * 4);
        }
    };

    issue(0, 0);  cp_commit();
    issue(1, 32); cp_commit();

    for (int kbi = 0; kbi < 32; kbi++) {
        cp_wait<1>();
        __syncthreads();
        const uint32_t* as = (const uint32_t*)(As + (kbi % 3) * 128 * 36);
        const uint32_t* bs = (const uint32_t*)(Bs + (kbi % 3) * 128 * 36);
#pragma unroll
        for (int kk = 0; kk < 32; kk += 8) {
            uint32_t a[4][4], b[4][2];
#pragma unroll
            for (int mt = 0; mt < 4; mt++) {
                int r0 = wm * 64 + mt * 16 + g;
                a[mt][0] = as[r0 * 36 + kk + tg];
                a[mt][1] = as[(r0 + 8) * 36 + kk + tg];
                a[mt][2] = as[r0 * 36 + kk + 4 + tg];
                a[mt][3] = as[(r0 + 8) * 36 + kk + 4 + tg];
            }
#pragma unroll
            for (int nt = 0; nt < 4; nt++) {
                int nr = wn * 32 + nt * 8 + g;
                b[nt][0] = bs[nr * 36 + kk + tg];
                b[nt][1] = bs[nr * 36 + kk + 4 + tg];
            }
#pragma unroll
            for (int mt = 0; mt < 4; mt++)
#pragma unroll
                for (int nt = 0; nt < 4; nt++) mma_tf32(acc[mt][nt], a[mt], b[nt]);
        }
        if (kbi + 2 < 32) issue((kbi + 2) % 3, (kbi + 2) * 32);
        cp_commit();
    }

    // epilogue
#pragma unroll
    for (int mt = 0; mt < 4; mt++) {
#pragma unroll
        for (int nt = 0; nt < 4; nt++) {
            int row = m0 + wm * 64 + mt * 16 + g;
            int col = n0 + wn * 32 + nt * 8 + 2 * tg;
#pragma unroll
            for (int h = 0; h < 2; h++) {
                int gr = row + h * 8;
                float b0, b1;
                float v0 = acc[mt][nt][h * 2 + 0];
                float v1 = acc[mt][nt][h * 2 + 1];
                if (mode == 0) { b0 = g_bg[col]; b1 = g_bg[col + 1]; }
                else           { b0 = bias_post[col]; b1 = bias_post[col + 1]; }
                float2 v = make_float2(v0 + b0, v1 + b1);
                if (mode == 0) {
                    *(float2*)(g_Gpre + (size_t)gr * 4096 + col) = v;
                } else {
                    size_t o = ((size_t)(gr & 63) * 512 + (gr >> 6)) * 1024 + col;
                    *(float2*)(Cpost + o) = v;
                }
            }
        }
    }
}

// ---------------- persistent recurrence: 128 CTAs x 512 thr, 512 steps -----
// CTA owns gate columns [n0, n0+32) = units [n0/4, n0/4+8).
// Split-K x4: warpgroup wg (= wid>>2, 4 warps each) computes K-quarter
// [wg*256,(wg+1)*256). Warp tile 16x32: warp wm covers rows wm*16..+15,
// ALL 32 gate cols (4 mma share one A fragment -> 1536B crossbar / 4 mma).
// SMEM: Bf (fragment-packed W_h, 128KB) | Ast (3 stages x [4 wgq][64][20])
//       | Gs (Gpre[t] tile 64x32). 4 partials combined in gate exchange.
static const int AST_Q     = 64 * 20;                 // 1280 floats per quarter
static const int AST_STAGE = 4 * AST_Q;               // 5120 floats per stage
static const int REC_SMEM  = (32768 + 3 * AST_STAGE + 2048) * 4;  // 200704 B

__global__ void __launch_bounds__(512) k_rec() {
    extern __shared__ float smr[];
    float* Bf  = smr;                     // [128 k8][2 half][32 lane][4] = 128KB
    float* Ast = smr + 32768;             // 3 stages [4][64][20]; aliased as gb
    float* Gs  = smr + 32768 + 3 * AST_STAGE;   // [64][32] Gpre tile

    const int tid = threadIdx.x, lane = tid & 31, wid = tid >> 5;
    const int wg = wid >> 2;              // warpgroup: K quarter (0..3)
    const int wm = wid & 3;               // m-warp within wg
    const int g = lane >> 2, tg = lane & 3;
    const int n0 = blockIdx.x * 32;
    const int bid = blockIdx.x;

    // ---- build fragment-packed W_h slice in SMEM (once; layout unchanged) ----
#pragma unroll 4
    for (int e = tid; e < 8192; e += 512) {
        int lane_e = e & 31, wn_e = (e >> 5) & 1, k8 = e >> 6;
        int ge = lane_e >> 2, tge = lane_e & 3;
        const float* w0 = g_WhT + (size_t)(n0 + wn_e * 16 + ge) * 1024 + k8 * 8 + tge;
        float4 v;
        v.x = w0[0];
        v.y = w0[4];
        v.z = w0[8 * 1024];
        v.w = w0[8 * 1024 + 4];
        *(float4*)(Bf + (size_t)e * 4) = v;
    }

    // ---- cell state in registers (1 item/thread) ----
    const int eb = tid >> 3, eu = tid & 7;           // elementwise (b, unit)
    float creg = g_c[(size_t)eb * 1024 + (n0 >> 2) + eu];

    // ---- barrier base: all flags equal at launch start (monotonic) ----
    __shared__ unsigned sh_base;
    if (tid == 0) sh_base = ldacq(&g_flags[bid * 32]);
    __syncthreads();
    const unsigned base = sh_base;

    // per-lane fragment base into Bf (float4 units): entry (k8, half, lane)
    const float4* bfl = (const float4*)Bf + lane;
    const int k8off = wg * 32;            // wg's K quarter in k8 units

    for (int t = 0; t < 512; t++) {
        const float* hin  = (t == 0) ? g_h0 : g_Hall + (size_t)(t - 1) * 64 * 1024;
        float* hall       = g_Hall + (size_t)t * 64 * 1024;
        const float* gpre = g_Gpre + (size_t)t * 64 * 4096;

        // stage loads all 4 K-quarters: 1024 float4 / 512 thr = 2 each
        auto issueA = [&](int stg, int kb) {     // kb = kbi*16 within quarter
            float* as = Ast + stg * AST_STAGE;
#pragma unroll
            for (int r = 0; r < 2; r++) {
                int f = tid + r * 512;            // 0..1023
                int c4 = f & 3, rw = f >> 2;
                int wgq = rw >> 6, row = rw & 63;
                cpa16(&as[wgq * AST_Q + row * 20 + c4 * 4],
                      hin + (size_t)row * 1024 + wgq * 256 + kb + c4 * 4);
            }
        };

        float acc[4][4];
#pragma unroll
        for (int i = 0; i < 4; i++)
#pragma unroll
            for (int k = 0; k < 4; k++) acc[i][k] = 0.f;

        // prefill: Gs (1 float4/thread) rides with stage0; then stage1
        {
            int row = tid >> 3, c4 = tid & 7;
            cpa16(&Gs[row * 32 + c4 * 4],
                  gpre + (size_t)row * 4096 + n0 + c4 * 4);
        }
        issueA(0, 0);  cp_commit();
        issueA(1, 16); cp_commit();

        for (int kbi = 0; kbi < 16; kbi++) {
            cp_wait<1>();
            __syncthreads();
            const uint32_t* as = (const uint32_t*)(Ast + (kbi % 3) * AST_STAGE
                                                   + wg * AST_Q);
#pragma unroll
            for (int kk = 0; kk < 16; kk += 8) {
                int k8 = k8off + kbi * 2 + (kk >> 3);
                uint32_t a[4];
                int r0 = wm * 16 + g;
                a[0] = as[r0 * 20 + kk + tg];
                a[1] = as[(r0 + 8) * 20 + kk + tg];
                a[2] = as[r0 * 20 + kk + 4 + tg];
                a[3] = as[(r0 + 8) * 20 + kk + 4 + tg];
                float4 bv0 = bfl[(k8 * 2 + 0) * 32];
                float4 bv1 = bfl[(k8 * 2 + 1) * 32];
                uint32_t b0[2] = { __float_as_uint(bv0.x), __float_as_uint(bv0.y) };
                uint32_t b1[2] = { __float_as_uint(bv0.z), __float_as_uint(bv0.w) };
                uint32_t b2[2] = { __float_as_uint(bv1.x), __float_as_uint(bv1.y) };
                uint32_t b3[2] = { __float_as_uint(bv1.z), __float_as_uint(bv1.w) };
                mma_tf32(acc[0], a, b0);
                mma_tf32(acc[1], a, b1);
                mma_tf32(acc[2], a, b2);
                mma_tf32(acc[3], a, b3);
            }
            if (kbi + 2 < 16) issueA((kbi + 2) % 3, (kbi + 2) * 16);
            cp_commit();
        }

        // ---- gate exchange: each wg writes its partial into its region ----
        cp_wait<0>();
        __syncthreads();
        float* gb = Ast;                  // alias: [4 wg][64][36], cols 0..31
        float* gbw = Ast + wg * 2304;
#pragma unroll
        for (int nt = 0; nt < 4; nt++) {
            int row = wm * 16 + g, col = nt * 8 + 2 * tg;
            gbw[row * 36 + col]           = acc[nt][0];
            gbw[row * 36 + col + 1]       = acc[nt][1];
            gbw[(row + 8) * 36 + col]     = acc[nt][2];
            gbw[(row + 8) * 36 + col + 1] = acc[nt][3];
        }
        __syncthreads();

        // ---- fused LSTM elementwise: 512 items, 1 per thread ----
        {
            int cl = 4 * eu;
            int o = eb * 36 + cl;
            float gf = Gs[eb * 32 + cl]     + gb[o]          + gb[2304 + o]
                     + gb[4608 + o]         + gb[6912 + o];
            float gi = Gs[eb * 32 + cl + 1] + gb[o + 1]      + gb[2304 + o + 1]
                     + gb[4608 + o + 1]     + gb[6912 + o + 1];
            float gc = Gs[eb * 32 + cl + 2] + gb[o + 2]      + gb[2304 + o + 2]
                     + gb[4608 + o + 2]     + gb[6912 + o + 2];
            float go = Gs[eb * 32 + cl + 3] + gb[o + 3]      + gb[2304 + o + 3]
                     + gb[4608 + o + 3]     + gb[6912 + o + 3];
            float f  = sigm(gf);
            float i  = sigm(gi);
            float ch = tanh_f(gc);
            float oo = sigm(go);
            float cn = f * creg + i * ch;
            creg = cn;
            float hr = tf32r(oo * tanh_f(cn));
            hall[(size_t)eb * 1024 + (n0 >> 2) + eu] = hr;
        }

        // ---- flat all-poll grid barrier (monotonic flags) ----
        const unsigned target = base + (unsigned)t + 1u;
        __syncthreads();                            // all h writes done
        if (tid == 0) strel(&g_flags[bid * 32], target);
        if (tid < 128) {
            while ((int)(ldacq(&g_flags[tid * 32]) - target) < 0) __nanosleep(32);
        }
        __syncthreads();                            // all threads see new h
    }
}

// ---------------- launch -----------------------------------------------------
extern "C" void kernel_launch(void* const* d_in, const int* in_sizes, int n_in,
                              void* d_out, int out_size) {
    const float* x    = (const float*)d_in[0];
    const float* h0   = (const float*)d_in[1];
    const float* c0   = (const float*)d_in[2];
    const float* W_f  = (const float*)d_in[3];
    const float* b_f  = (const float*)d_in[4];
    const float* W_i  = (const float*)d_in[5];
    const float* b_i  = (const float*)d_in[6];
    const float* W_c  = (const float*)d_in[7];
    const float* b_c  = (const float*)d_in[8];
    const float* W_o  = (const float*)d_in[9];
    const float* b_o  = (const float*)d_in[10];
    const float* W_out = (const float*)d_in[11];
    const float* b_out = (const float*)d_in[12];
    float* out = (float*)d_out;

    cudaFuncSetAttribute(k_gemm, cudaFuncAttributeMaxDynamicSharedMemorySize, GEMM_SMEM);
    cudaFuncSetAttribute(k_rec,  cudaFuncAttributeMaxDynamicSharedMemorySize, REC_SMEM);

    // 5 launches; slot 4 = k_rec (this round's variable gets profiled).
    k_prepA<<<33024, 256>>>(x, b_f, b_i, b_c, b_o, h0, c0);
    k_prepB<<<9216, dim3(32, 8)>>>(W_f, W_i, W_c, W_o, W_out);

    // pre-GEMM: G_pre (M=32768, N=4096), 8192 CTAs supertiled
    k_gemm<<<8192, 256, GEMM_SMEM>>>(nullptr, nullptr, 0);

    // persistent recurrence: all 512 steps in one kernel
    k_rec<<<128, 512, REC_SMEM>>>();

    // post-GEMM: out (M=32768, N=1024), 2048 CTAs supertiled
    k_gemm<<<2048, 256, GEMM_SMEM>>>(out, b_out, 1);
}

// round 17
// speedup vs baseline: 1.1444x; 1.0386x over previous
#include <cuda_runtime.h>
#include <cstdint>
#include <math.h>

// ---------------------------------------------------------------------------
// LSTM  B=64 S=512 D=1024 H=1024 F=1024
//  1) G_pre = Xt @ Wx^T + b_g      (tf32 GEMM, M=32768 N=4096 K=1024)
//  2) ONE persistent kernel, 128 CTAs x 512 thr, 512 steps (R15 config):
//       gates = G_pre[t] + h@Wh^T ; fused LSTM elementwise
//  3) out = Hall @ Wo^T + b_out    (tf32 GEMM, M=32768 N=1024 K=1024)
// NEW (R16): GEMM operands pre-packed in GMEM in mma-fragment order:
//   A pane (128 rows x 1024 k): off = ((k8*2+wm)*4+mt)*128 + lane*4 + reg
//     with wm=r>>6, mt=(r>>4)&3, lane=4*(r&7)+(k&3), reg=((k>>2)&1)*2+((r>>3)&1)
//   B pane (128 cols x 1024 k): off = (((k8*4+wn)*2+p)*128) + (4*g+(k&3))*4
//     + (nt&1)*2 + ((k>>2)&1), with c=n&127, wn=c>>5, nt=(c>>3)&3, p=nt>>1, g=c&7
// Mainloop: 6 LDS.128 per k8 (was 24 LDS.32) -> LSU issue no longer binds.
// Gate columns interleaved: n = 4*unit + gate.
// ---------------------------------------------------------------------------

#define DEVINL __device__ __forceinline__

static const int PANE = 131072;                  // floats per 128x1024 pane

// ---------------- static device scratch (no runtime allocation) ------------
__device__ float g_XtP  [(size_t)256 * PANE];    // packed A panes of Xt
__device__ float g_HallP[(size_t)256 * PANE];    // packed A panes of Hall
__device__ float g_Gpre [(size_t)32768 * 4096];  // x-part of gates (+bias)
__device__ float g_WxP  [(size_t)32 * PANE];     // packed B panes, gate weights
__device__ float g_WoP  [(size_t)8 * PANE];      // packed B panes, W_out
__device__ float g_WhT  [(size_t)4096 * 1024];   // [n][k] interleaved, h rows
__device__ float g_bg   [4096];                  // gate bias, interleaved
__device__ float g_h    [2][64 * 1024];          // row-major h ping-pong
__device__ float g_c    [64 * 1024];             // cell state (init only)

// grid-barrier state: monotonic counters (never reset; base read per launch)
__device__ unsigned g_flags[128 * 32];           // flag i at [i*32] (own 128B line)

// ---------------- helpers ---------------------------------------------------
DEVINL uint32_t f2tf32(float x) {
    uint32_t r; asm("cvt.rna.tf32.f32 %0, %1;" : "=r"(r) : "f"(x)); return r;
}
DEVINL float tf32r(float x) { return __uint_as_float(f2tf32(x)); }

DEVINL void cpa16(void* dst, const void* src) {
    uint32_t d = (uint32_t)__cvta_generic_to_shared(dst);
    asm volatile("cp.async.cg.shared.global [%0], [%1], 16;\n" :: "r"(d), "l"(src));
}
DEVINL void cp_commit() { asm volatile("cp.async.commit_group;\n"); }
template <int N> DEVINL void cp_wait() { asm volatile("cp.async.wait_group %0;\n" :: "n"(N)); }

DEVINL void mma_tf32(float* c, const uint32_t* a, const uint32_t* b) {
    asm volatile(
        "mma.sync.aligned.m16n8k8.row.col.f32.tf32.tf32.f32 "
        "{%0,%1,%2,%3},{%4,%5,%6,%7},{%8,%9},{%0,%1,%2,%3};\n"
        : "+f"(c[0]), "+f"(c[1]), "+f"(c[2]), "+f"(c[3])
        : "r"(a[0]), "r"(a[1]), "r"(a[2]), "r"(a[3]), "r"(b[0]), "r"(b[1]));
}
DEVINL float sigm(float x)   { return 1.f / (1.f + __expf(-x)); }
DEVINL float tanh_f(float x) { return 2.f / (1.f + __expf(-2.f * x)) - 1.f; }

DEVINL unsigned ldacq(const unsigned* p) {
    unsigned v; asm volatile("ld.acquire.gpu.global.u32 %0, [%1];" : "=r"(v) : "l"(p)); return v;
}
DEVINL void strel(unsigned* p, unsigned v) {
    asm volatile("st.release.gpu.global.u32 [%0], %1;" :: "l"(p), "r"(v));
}

// packed-A offset within a pane for (row r in [0,128), k in [0,1024))
DEVINL int apack_off(int r, int k) {
    int k8 = k >> 3, wm = r >> 6, mt = (r >> 4) & 3;
    int lane = 4 * (r & 7) + (k & 3);
    int reg  = (((k >> 2) & 1) << 1) | ((r >> 3) & 1);
    return ((k8 * 2 + wm) * 4 + mt) * 128 + lane * 4 + reg;
}
// packed-B offset within a pane for (col c in [0,128), k in [0,1024))
DEVINL int bpack_off(int c, int k) {
    int k8 = k >> 3, wn = c >> 5, nt = (c >> 3) & 3, g = c & 7;
    return (((k8 * 4 + wn) * 2 + (nt >> 1)) * 32 + 4 * g + (k & 3)) * 4
           + (nt & 1) * 2 + ((k >> 2) & 1);
}

// ---------------- prepA: x -> packed A panes + bias/state init --------------
__global__ void __launch_bounds__(256) k_prepA(
        const float* __restrict__ x,
        const float* __restrict__ bf, const float* __restrict__ bi,
        const float* __restrict__ bc, const float* __restrict__ bo,
        const float* __restrict__ h0, const float* __restrict__ c0) {
    if (blockIdx.x < 32768) {
        size_t p = (size_t)blockIdx.x * 256 + threadIdx.x;
        int d4 = (int)(p & 255);
        size_t m = p >> 8;                       // row index = t*64+b
        int b = (int)(m & 63), t = (int)(m >> 6);
        float4 v = *(const float4*)(x + ((size_t)b * 512 + t) * 1024 + (size_t)d4 * 4);
        float* pane = g_XtP + (m >> 7) * PANE;
        int r = (int)(m & 127), k = d4 * 4;
        pane[apack_off(r, k + 0)] = tf32r(v.x);
        pane[apack_off(r, k + 1)] = tf32r(v.y);
        pane[apack_off(r, k + 2)] = tf32r(v.z);
        pane[apack_off(r, k + 3)] = tf32r(v.w);
    } else {
        int i = (blockIdx.x - 32768) * 256 + threadIdx.x;   // 0..65535
        if (i < 4096) {
            int u = i >> 2, gt = i & 3;
            const float* b = (gt == 0) ? bf : (gt == 1) ? bi : (gt == 2) ? bc : bo;
            g_bg[i] = b[u];
        }
        g_h[0][i] = tf32r(h0[i]);
        g_c[i]    = c0[i];
    }
}

// ---------------- prep_w: gate weights -> packed WxP / row-major WhT --------
__global__ void k_prep_w(const float* __restrict__ Wf, const float* __restrict__ Wi,
                         const float* __restrict__ Wc, const float* __restrict__ Wo) {
    __shared__ float tile[32][33];
    int tx = threadIdx.x, ty = threadIdx.y;
    int bid = blockIdx.x;
    int s    = bid >> 12;         // 0 = x rows, 1 = h rows
    int gate = (bid >> 10) & 3;
    int kt   = (bid >> 5) & 31;
    int ut   = bid & 31;
    const float* W = (gate == 0) ? Wf : (gate == 1) ? Wi : (gate == 2) ? Wc : Wo;
#pragma unroll
    for (int r = 0; r < 4; r++) {
        int k = kt * 32 + ty + r * 8;
        tile[ty + r * 8][tx] = W[(size_t)(s * 1024 + k) * 1024 + ut * 32 + tx];
    }
    __syncthreads();
#pragma unroll
    for (int r = 0; r < 4; r++) {
        int ul = ty + r * 8;
        int n = 4 * (ut * 32 + ul) + gate;
        int k = kt * 32 + tx;
        float v = tf32r(tile[tx][ul]);
        if (s) g_WhT[(size_t)n * 1024 + k] = v;
        else   g_WxP[(size_t)(n >> 7) * PANE + bpack_off(n & 127, k)] = v;
    }
}

// ---------------- prep_wout: W_out -> packed WoP ------------------------------
__global__ void k_prep_wout(const float* __restrict__ Wout) {
    __shared__ float tile[32][33];
    int tx = threadIdx.x, ty = threadIdx.y;
    int ft = blockIdx.x & 31, ht = blockIdx.x >> 5;
#pragma unroll
    for (int r = 0; r < 4; r++) {
        int h = ht * 32 + ty + r * 8;
        tile[ty + r * 8][tx] = Wout[(size_t)h * 1024 + ft * 32 + tx];
    }
    __syncthreads();
#pragma unroll
    for (int r = 0; r < 4; r++) {
        int fl = ty + r * 8;
        int f = ft * 32 + fl;
        int k = ht * 32 + tx;
        g_WoP[(size_t)(f >> 7) * PANE + bpack_off(f & 127, k)] = tf32r(tile[tx][fl]);
    }
}

// ---------------- big tf32 GEMM on packed operands ---------------------------
// BM=128 BN=128 BK=32, 256 thr, 3-stage, compute-then-issue, 2 CTAs/SM.
// Stage = linear 16KB pane chunk per operand; mainloop = 6 LDS.128 per k8.
static const int GEMM_SMEM = 3 * 2 * 4096 * 4;   // 98304 B

__global__ void __launch_bounds__(256) k_gemm(float* __restrict__ Cpost,
                                              const float* __restrict__ bias_post,
                                              int mode) {
    extern __shared__ float sm[];
    const float* A  = mode ? g_HallP : g_XtP;
    const float* BT = mode ? g_WoP   : g_WxP;
    float* As = sm;                    // [3][4096]
    float* Bs = sm + 3 * 4096;         // [3][4096]

    const int tid = threadIdx.x, lane = tid & 31, wid = tid >> 5;
    const int wm = wid & 1, wn = wid >> 1;          // 2 x 4 warps
    const int g = lane >> 2, tg = lane & 3;

    int mi, ni;
    if (mode == 0) {                     // 32 n-blocks
        int sup = blockIdx.x >> 8, rem = blockIdx.x & 255;
        mi = sup * 8 + (rem & 7); ni = rem >> 3;
    } else {                             // 8 n-blocks
        int sup = blockIdx.x >> 6, rem = blockIdx.x & 63;
        mi = sup * 8 + (rem & 7); ni = rem >> 3;
    }
    const float* Ablk = A  + (size_t)mi * PANE;
    const float* Bblk = BT + (size_t)ni * PANE;
    const int m0 = mi * 128;
    const int n0 = ni * 128;

    float acc[4][4][4];
#pragma unroll
    for (int i = 0; i < 4; i++)
#pragma unroll
        for (int j = 0; j < 4; j++)
#pragma unroll
            for (int k = 0; k < 4; k++) acc[i][j][k] = 0.f;

    auto issue = [&](int stg, int kbi) {
        float* as = As + stg * 4096;
        float* bs = Bs + stg * 4096;
        const float* asrc = Ablk + kbi * 4096;
        const float* bsrc = Bblk + kbi * 4096;
#pragma unroll
        for (int r = 0; r < 4; r++) {
            int idx = tid + r * 256;              // float4 index, 1024 total
            cpa16(&as[idx * 4], asrc + (size_t)idx * 4);
        }
#pragma unroll
        for (int r = 0; r < 4; r++) {
            int idx = tid + r * 256;
            cpa16(&bs[idx * 4], bsrc + (size_t)idx * 4);
        }
    };

    issue(0, 0); cp_commit();
    issue(1, 1); cp_commit();

    for (int kbi = 0; kbi < 32; kbi++) {
        cp_wait<1>();
        __syncthreads();
        const float* as = As + (kbi % 3) * 4096;
        const float* bs = Bs + (kbi % 3) * 4096;
#pragma unroll
        for (int k8l = 0; k8l < 4; k8l++) {
            const float4* a4 = (const float4*)(as + k8l * 1024) + wm * 128 + lane;
            const float4* b4 = (const float4*)(bs + k8l * 1024) + wn * 64 + lane;
            uint32_t a[4][4];
#pragma unroll
            for (int mt = 0; mt < 4; mt++) {
                float4 av = a4[mt * 32];
                a[mt][0] = __float_as_uint(av.x);
                a[mt][1] = __float_as_uint(av.y);
                a[mt][2] = __float_as_uint(av.z);
                a[mt][3] = __float_as_uint(av.w);
            }
            float4 bv0 = b4[0];
            float4 bv1 = b4[32];
            uint32_t b[4][2] = {
                { __float_as_uint(bv0.x), __float_as_uint(bv0.y) },
                { __float_as_uint(bv0.z), __float_as_uint(bv0.w) },
                { __float_as_uint(bv1.x), __float_as_uint(bv1.y) },
                { __float_as_uint(bv1.z), __float_as_uint(bv1.w) } };
#pragma unroll
            for (int mt = 0; mt < 4; mt++)
#pragma unroll
                for (int nt = 0; nt < 4; nt++) mma_tf32(acc[mt][nt], a[mt], b[nt]);
        }
        if (kbi + 2 < 32) issue((kbi + 2) % 3, kbi + 2);
        cp_commit();
    }

    // epilogue (identical mapping to previous rounds)
#pragma unroll
    for (int mt = 0; mt < 4; mt++) {
#pragma unroll
        for (int nt = 0; nt < 4; nt++) {
            int row = m0 + wm * 64 + mt * 16 + g;
            int col = n0 + wn * 32 + nt * 8 + 2 * tg;
#pragma unroll
            for (int h = 0; h < 2; h++) {
                int gr = row + h * 8;
                float b0, b1;
                float v0 = acc[mt][nt][h * 2 + 0];
                float v1 = acc[mt][nt][h * 2 + 1];
                if (mode == 0) { b0 = g_bg[col]; b1 = g_bg[col + 1]; }
                else           { b0 = bias_post[col]; b1 = bias_post[col + 1]; }
                float2 v = make_float2(v0 + b0, v1 + b1);
                if (mode == 0) {
                    *(float2*)(g_Gpre + (size_t)gr * 4096 + col) = v;
                } else {
                    size_t o = ((size_t)(gr & 63) * 512 + (gr >> 6)) * 1024 + col;
                    *(float2*)(Cpost + o) = v;
                }
            }
        }
    }
}

// ---------------- persistent recurrence (R15 winner + packed-h writeback) ---
// 128 CTAs x 512 thr. Split-K x4, warp tile 16x32, BK=16, 3 stages.
static const int AST_Q     = 64 * 20;                 // 1280 floats per quarter
static const int AST_STAGE = 4 * AST_Q;               // 5120 floats per stage
static const int REC_SMEM  = (32768 + 3 * AST_STAGE + 2048) * 4;  // 200704 B

__global__ void __launch_bounds__(512) k_rec() {
    extern __shared__ float smr[];
    float* Bf  = smr;                     // fragment-packed W_h slice, 128KB
    float* Ast = smr + 32768;             // 3 stages [4][64][20]; aliased as gb
    float* Gs  = smr + 32768 + 3 * AST_STAGE;   // [64][32] Gpre tile

    const int tid = threadIdx.x, lane = tid & 31, wid = tid >> 5;
    const int wg = wid >> 2;              // warpgroup: K quarter (0..3)
    const int wm = wid & 3;               // m-warp within wg
    const int g = lane >> 2, tg = lane & 3;
    const int n0 = blockIdx.x * 32;
    const int bid = blockIdx.x;

    // ---- build fragment-packed W_h slice in SMEM (once) ----
#pragma unroll 4
    for (int e = tid; e < 8192; e += 512) {
        int lane_e = e & 31, wn_e = (e >> 5) & 1, k8 = e >> 6;
        int ge = lane_e >> 2, tge = lane_e & 3;
        const float* w0 = g_WhT + (size_t)(n0 + wn_e * 16 + ge) * 1024 + k8 * 8 + tge;
        float4 v;
        v.x = w0[0];
        v.y = w0[4];
        v.z = w0[8 * 1024];
        v.w = w0[8 * 1024 + 4];
        *(float4*)(Bf + (size_t)e * 4) = v;
    }

    // ---- cell state in registers (1 item/thread) ----
    const int eb = tid >> 3, eu = tid & 7;           // elementwise (b, unit)
    float creg = g_c[(size_t)eb * 1024 + (n0 >> 2) + eu];

    // ---- barrier base ----
    __shared__ unsigned sh_base;
    if (tid == 0) sh_base = ldacq(&g_flags[bid * 32]);
    __syncthreads();
    const unsigned base = sh_base;

    const float4* bfl = (const float4*)Bf + lane;
    const int k8off = wg * 32;            // wg's K quarter in k8 units

    for (int t = 0; t < 512; t++) {
        const float* hin  = g_h[t & 1];
        float* hout       = g_h[(t + 1) & 1];
        const float* gpre = g_Gpre + (size_t)t * 64 * 4096;

        auto issueA = [&](int stg, int kb) {     // kb = kbi*16 within quarter
            float* as = Ast + stg * AST_STAGE;
#pragma unroll
            for (int r = 0; r < 2; r++) {
                int f = tid + r * 512;            // 0..1023
                int c4 = f & 3, rw = f >> 2;
                int wgq = rw >> 6, row = rw & 63;
                cpa16(&as[wgq * AST_Q + row * 20 + c4 * 4],
                      hin + (size_t)row * 1024 + wgq * 256 + kb + c4 * 4);
            }
        };

        float acc[4][4];
#pragma unroll
        for (int i = 0; i < 4; i++)
#pragma unroll
            for (int k = 0; k < 4; k++) acc[i][k] = 0.f;

        {
            int row = tid >> 3, c4 = tid & 7;
            cpa16(&Gs[row * 32 + c4 * 4],
                  gpre + (size_t)row * 4096 + n0 + c4 * 4);
        }
        issueA(0, 0);  cp_commit();
        issueA(1, 16); cp_commit();

        for (int kbi = 0; kbi < 16; kbi++) {
            cp_wait<1>();
            __syncthreads();
            const uint32_t* as = (const uint32_t*)(Ast + (kbi % 3) * AST_STAGE
                                                   + wg * AST_Q);
#pragma unroll
            for (int kk = 0; kk < 16; kk += 8) {
                int k8 = k8off + kbi * 2 + (kk >> 3);
                uint32_t a[4];
                int r0 = wm * 16 + g;
                a[0] = as[r0 * 20 + kk + tg];
                a[1] = as[(r0 + 8) * 20 + kk + tg];
                a[2] = as[r0 * 20 + kk + 4 + tg];
                a[3] = as[(r0 + 8) * 20 + kk + 4 + tg];
                float4 bv0 = bfl[(k8 * 2 + 0) * 32];
                float4 bv1 = bfl[(k8 * 2 + 1) * 32];
                uint32_t b0[2] = { __float_as_uint(bv0.x), __float_as_uint(bv0.y) };
                uint32_t b1[2] = { __float_as_uint(bv0.z), __float_as_uint(bv0.w) };
                uint32_t b2[2] = { __float_as_uint(bv1.x), __float_as_uint(bv1.y) };
                uint32_t b3[2] = { __float_as_uint(bv1.z), __float_as_uint(bv1.w) };
                mma_tf32(acc[0], a, b0);
                mma_tf32(acc[1], a, b1);
                mma_tf32(acc[2], a, b2);
                mma_tf32(acc[3], a, b3);
            }
            if (kbi + 2 < 16) issueA((kbi + 2) % 3, (kbi + 2) * 16);
            cp_commit();
        }

        // ---- gate exchange ----
        cp_wait<0>();
        __syncthreads();
        float* gb = Ast;                  // alias: [4 wg][64][36], cols 0..31
        float* gbw = Ast + wg * 2304;
#pragma unroll
        for (int nt = 0; nt < 4; nt++) {
            int row = wm * 16 + g, col = nt * 8 + 2 * tg;
            gbw[row * 36 + col]           = acc[nt][0];
            gbw[row * 36 + col + 1]       = acc[nt][1];
            gbw[(row + 8) * 36 + col]     = acc[nt][2];
            gbw[(row + 8) * 36 + col + 1] = acc[nt][3];
        }
        __syncthreads();

        // ---- fused LSTM elementwise ----
        {
            int cl = 4 * eu;
            int o = eb * 36 + cl;
            float gf = Gs[eb * 32 + cl]     + gb[o]          + gb[2304 + o]
                     + gb[4608 + o]         + gb[6912 + o];
            float gi = Gs[eb * 32 + cl + 1] + gb[o + 1]      + gb[2304 + o + 1]
                     + gb[4608 + o + 1]     + gb[6912 + o + 1];
            float gc = Gs[eb * 32 + cl + 2] + gb[o + 2]      + gb[2304 + o + 2]
                     + gb[4608 + o + 2]     + gb[6912 + o + 2];
            float go = Gs[eb * 32 + cl + 3] + gb[o + 3]      + gb[2304 + o + 3]
                     + gb[4608 + o + 3]     + gb[6912 + o + 3];
            float f  = sigm(gf);
            float i  = sigm(gi);
            float ch = tanh_f(gc);
            float oo = sigm(go);
            float cn = f * creg + i * ch;
            creg = cn;
            float hr = tf32r(oo * tanh_f(cn));
            int U = (n0 >> 2) + eu;
            hout[(size_t)eb * 1024 + U] = hr;               // row-major ping-pong
            int r = ((t & 1) << 6) | eb;                    // packed Hall pane
            g_HallP[(size_t)(t >> 1) * PANE + apack_off(r, U)] = hr;
        }

        // ---- flat all-poll grid barrier ----
        const unsigned target = base + (unsigned)t + 1u;
        __syncthreads();
        if (tid == 0) strel(&g_flags[bid * 32], target);
        if (tid < 128) {
            while ((int)(ldacq(&g_flags[tid * 32]) - target) < 0) __nanosleep(32);
        }
        __syncthreads();
    }
}

// ---------------- launch -----------------------------------------------------
extern "C" void kernel_launch(void* const* d_in, const int* in_sizes, int n_in,
                              void* d_out, int out_size) {
    const float* x    = (const float*)d_in[0];
    const float* h0   = (const float*)d_in[1];
    const float* c0   = (const float*)d_in[2];
    const float* W_f  = (const float*)d_in[3];
    const float* b_f  = (const float*)d_in[4];
    const float* W_i  = (const float*)d_in[5];
    const float* b_i  = (const float*)d_in[6];
    const float* W_c  = (const float*)d_in[7];
    const float* b_c  = (const float*)d_in[8];
    const float* W_o  = (const float*)d_in[9];
    const float* b_o  = (const float*)d_in[10];
    const float* W_out = (const float*)d_in[11];
    const float* b_out = (const float*)d_in[12];
    float* out = (float*)d_out;

    cudaFuncSetAttribute(k_gemm, cudaFuncAttributeMaxDynamicSharedMemorySize, GEMM_SMEM);
    cudaFuncSetAttribute(k_rec,  cudaFuncAttributeMaxDynamicSharedMemorySize, REC_SMEM);

    // 6 launches; slot 4 = pre-GEMM (verify tensor% jump from packing).
    k_prepA<<<33024, 256>>>(x, b_f, b_i, b_c, b_o, h0, c0);
    k_prep_w<<<8192, dim3(32, 8)>>>(W_f, W_i, W_c, W_o);
    k_prep_wout<<<1024, dim3(32, 8)>>>(W_out);

    // pre-GEMM: G_pre (M=32768, N=4096), 8192 CTAs supertiled
    k_gemm<<<8192, 256, GEMM_SMEM>>>(nullptr, nullptr, 0);

    // persistent recurrence: all 512 steps in one kernel
    k_rec<<<128, 512, REC_SMEM>>>();

    // post-GEMM: out (M=32768, N=1024), 2048 CTAs supertiled
    k_gemm<<<2048, 256, GEMM_SMEM>>>(out, b_out, 1);
}